// round 7
// baseline (speedup 1.0000x reference)
#include <cuda_runtime.h>
#include <cstdint>

// Problem dims (fixed by the reference)
#define BATCH 8
#define SEQ   2048
#define DMODEL 1024
#define NROWS (BATCH * SEQ)          // 16384

// Scratch
__device__ float g_rq[(size_t)NROWS * DMODEL];              // rounded inputs
__device__ float g_rk[(size_t)NROWS * DMODEL];
__device__ float g_rv[(size_t)NROWS * DMODEL];
__device__ float g_wt[(size_t)3 * DMODEL * DMODEL];         // W^T rounded
__device__ float g_proj_q[(size_t)NROWS * DMODEL];          // rounded projections
__device__ float g_proj_k[(size_t)NROWS * DMODEL];
__device__ float g_proj_v[(size_t)NROWS * DMODEL];
__device__ float g_vt[(size_t)BATCH * DMODEL * SEQ];        // v^T per batch
__device__ float g_scores[(size_t)BATCH * SEQ * SEQ];

// ---------------------------------------------------------------------------
// Helpers
// ---------------------------------------------------------------------------
__device__ __forceinline__ float rna_tf32(float x) {
    uint32_t r; asm("cvt.rna.tf32.f32 %0, %1;" : "=r"(r) : "f"(x));
    return __uint_as_float(r);
}

__device__ __forceinline__ void mma8(float* c,
                                     uint32_t a0, uint32_t a1, uint32_t a2, uint32_t a3,
                                     uint32_t b0, uint32_t b1) {
    asm volatile(
        "mma.sync.aligned.m16n8k8.row.col.f32.tf32.tf32.f32 "
        "{%0,%1,%2,%3},{%4,%5,%6,%7},{%8,%9},{%0,%1,%2,%3};\n"
        : "+f"(c[0]), "+f"(c[1]), "+f"(c[2]), "+f"(c[3])
        : "r"(a0), "r"(a1), "r"(a2), "r"(a3), "r"(b0), "r"(b1));
}

__device__ __forceinline__ void ldsm4(uint32_t* r, uint32_t saddr) {
    asm volatile("ldmatrix.sync.aligned.m8n8.x4.shared.b16 {%0,%1,%2,%3}, [%4];"
        : "=r"(r[0]), "=r"(r[1]), "=r"(r[2]), "=r"(r[3]) : "r"(saddr));
}
__device__ __forceinline__ void ldsm2(uint32_t* r, uint32_t saddr) {
    asm volatile("ldmatrix.sync.aligned.m8n8.x2.shared.b16 {%0,%1}, [%2];"
        : "=r"(r[0]), "=r"(r[1]) : "r"(saddr));
}

__device__ __forceinline__ void cpa16(uint32_t saddr, const void* g) {
    asm volatile("cp.async.cg.shared.global [%0], [%1], 16;\n" :: "r"(saddr), "l"(g));
}
#define CPA_COMMIT()  asm volatile("cp.async.commit_group;\n")
#define CPA_WAIT1()   asm volatile("cp.async.wait_group 1;\n" ::: "memory")
#define CPA_WAIT0()   asm volatile("cp.async.wait_group 0;\n" ::: "memory")

// Tiles (stride-36 u32 rows, conflict-free for LDSM gathers and cp.async):
// A: 128 rows x 32 k; B: 256 rows x 32 k. 3 stages.
#define A_BYTES    (128 * 36 * 4)        // 18432
#define B_BYTES    (256 * 36 * 4)        // 36864
#define STG_BYTES  (A_BYTES + B_BYTES)   // 55296
#define SMEM_BYTES (3 * STG_BYTES)       // 165888

// ---------------------------------------------------------------------------
// Unified NT mainloop: acc[4][8][4] += A[128,K] . B[256,K]^T
// 8 warps, 2x4 grid, warp tile 64x64. 3-stage ring, depth-2 prefetch,
// ONE __syncthreads per k-tile.
// ---------------------------------------------------------------------------
__device__ __forceinline__ void mainloop_nt(
    const float* __restrict__ Ag, int lda,
    const float* __restrict__ Bg, int ldb,
    int T, uint32_t smb, float acc[4][8][4])
{
    const int t = threadIdx.x;
    const int warp = t >> 5, lane = t & 31;
    const int wm = warp >> 2, wn = warp & 3;

    // ldmatrix per-lane byte offsets (relative to tile base)
    const int rowin = lane & 7;
    const int tA = lane >> 3;                      // x4: (m8, k4) tile select
    uint32_t offA[4], offB[8];
    #pragma unroll
    for (int mt = 0; mt < 4; mt++) {
        const int r = wm * 64 + mt * 16 + (tA & 1) * 8 + rowin;
        offA[mt] = (uint32_t)((r * 36 + (tA >> 1) * 4) * 4);
    }
    const int tB = (lane >> 3) & 1;                // x2: k4 tile select
    #pragma unroll
    for (int nt = 0; nt < 8; nt++) {
        const int r = wn * 64 + nt * 8 + rowin;
        offB[nt] = (uint32_t)((r * 36 + tB * 4) * 4);
    }

    auto issue = [&](int tt) {
        const int s = tt % 3;
        const uint32_t sa = smb + s * STG_BYTES;
        const float* ak = Ag + tt * 32;
        #pragma unroll
        for (int i = 0; i < 4; i++) {              // A: 1024 chunks / 256 thr
            const int ch = t + i * 256, r = ch >> 3, c4 = (ch & 7) * 4;
            cpa16(sa + (r * 36 + c4) * 4, ak + (size_t)r * lda + c4);
        }
        const uint32_t sb = sa + A_BYTES;
        const float* bk = Bg + tt * 32;
        #pragma unroll
        for (int i = 0; i < 8; i++) {              // B: 2048 chunks / 256 thr
            const int ch = t + i * 256, r = ch >> 3, c4 = (ch & 7) * 4;
            cpa16(sb + (r * 36 + c4) * 4, bk + (size_t)r * ldb + c4);
        }
        CPA_COMMIT();
    };

    issue(0);
    if (1 < T) issue(1);

    for (int tt = 0; tt < T; tt++) {
        if (tt + 1 < T) { CPA_WAIT1(); } else { CPA_WAIT0(); }
        __syncthreads();
        if (tt + 2 < T) issue(tt + 2);

        const uint32_t abase = smb + (tt % 3) * STG_BYTES;
        const uint32_t bbase = abase + A_BYTES;

        #pragma unroll
        for (int ks = 0; ks < 4; ks++) {
            const uint32_t kboff = ks * 32;        // 8 k * 4B
            uint32_t af[4][4];
            #pragma unroll
            for (int mt = 0; mt < 4; mt++) ldsm4(af[mt], abase + offA[mt] + kboff);
            #pragma unroll
            for (int h = 0; h < 2; h++) {
                uint32_t bf[4][2];
                #pragma unroll
                for (int nt = 0; nt < 4; nt++)
                    ldsm2(bf[nt], bbase + offB[h * 4 + nt] + kboff);
                #pragma unroll
                for (int mt = 0; mt < 4; mt++)
                    #pragma unroll
                    for (int nt = 0; nt < 4; nt++)
                        mma8(acc[mt][h * 4 + nt],
                             af[mt][0], af[mt][1], af[mt][2], af[mt][3],
                             bf[nt][0], bf[nt][1]);
            }
        }
    }
}

// ---------------------------------------------------------------------------
// Pre-pass 1: round Q,K,V to tf32-rna
// ---------------------------------------------------------------------------
__global__ __launch_bounds__(256) void round_qkv(
    const float* __restrict__ Q, const float* __restrict__ K, const float* __restrict__ V)
{
    const size_t n4 = (size_t)NROWS * DMODEL / 4;
    for (size_t i = (size_t)blockIdx.x * blockDim.x + threadIdx.x; i < n4;
         i += (size_t)gridDim.x * blockDim.x) {
        float4 a;
        a = ((const float4*)Q)[i];
        ((float4*)g_rq)[i] = make_float4(rna_tf32(a.x), rna_tf32(a.y), rna_tf32(a.z), rna_tf32(a.w));
        a = ((const float4*)K)[i];
        ((float4*)g_rk)[i] = make_float4(rna_tf32(a.x), rna_tf32(a.y), rna_tf32(a.z), rna_tf32(a.w));
        a = ((const float4*)V)[i];
        ((float4*)g_rv)[i] = make_float4(rna_tf32(a.x), rna_tf32(a.y), rna_tf32(a.z), rna_tf32(a.w));
    }
}

// Pre-pass 2: W^T rounded. grid (32,32,3), block (32,8)
__global__ void wtrans_kernel(
    const float* __restrict__ Wq, const float* __restrict__ Wk, const float* __restrict__ Wv)
{
    const int which = blockIdx.z;
    const float* W = (which == 0) ? Wq : (which == 1) ? Wk : Wv;
    float* WT = g_wt + (size_t)which * DMODEL * DMODEL;
    __shared__ float tl[32][33];
    const int x0 = blockIdx.x * 32, y0 = blockIdx.y * 32;
    const int tx = threadIdx.x, ty = threadIdx.y;
    #pragma unroll
    for (int r = ty; r < 32; r += 8)
        tl[r][tx] = W[(size_t)(y0 + r) * DMODEL + x0 + tx];
    __syncthreads();
    #pragma unroll
    for (int r = ty; r < 32; r += 8)
        WT[(size_t)(x0 + r) * DMODEL + y0 + tx] = rna_tf32(tl[tx][r]);
}

// ---------------------------------------------------------------------------
// GEMM 1: projections (NT with W^T). grid = (DMODEL/256, NROWS/128, 3)
// ---------------------------------------------------------------------------
__global__ __launch_bounds__(256, 1) void proj_kernel(
    const float* __restrict__ bq, const float* __restrict__ bk, const float* __restrict__ bv)
{
    const int which = blockIdx.z;
    const float* A    = (which == 0) ? g_rq : (which == 1) ? g_rk : g_rv;
    const float* Bw   = g_wt + (size_t)which * DMODEL * DMODEL;
    const float* bias = (which == 0) ? bq : (which == 1) ? bk : bv;
    float* C          = (which == 0) ? g_proj_q : (which == 1) ? g_proj_k : g_proj_v;

    extern __shared__ uint32_t sm[];
    const uint32_t smb = (uint32_t)__cvta_generic_to_shared(sm);

    const int m0 = blockIdx.y * 128;
    const int n0 = blockIdx.x * 256;

    float acc[4][8][4];
    #pragma unroll
    for (int i = 0; i < 4; i++)
        #pragma unroll
        for (int j = 0; j < 8; j++)
            #pragma unroll
            for (int c = 0; c < 4; c++) acc[i][j][c] = 0.f;

    mainloop_nt(A + (size_t)m0 * DMODEL, DMODEL,
                Bw + (size_t)n0 * DMODEL, DMODEL,
                DMODEL / 32, smb, acc);

    const int t = threadIdx.x, warp = t >> 5, lane = t & 31;
    const int wm = warp >> 2, wn = warp & 3;
    const int g = lane >> 2, tq = lane & 3;

    #pragma unroll
    for (int mt = 0; mt < 4; mt++) {
        const int r0 = m0 + wm * 64 + mt * 16 + g;
        #pragma unroll
        for (int nt = 0; nt < 8; nt++) {
            const int c0 = n0 + wn * 64 + nt * 8 + tq * 2;
            const float b0 = bias[c0], b1 = bias[c0 + 1];
            float* p0 = &C[(size_t)r0 * DMODEL + c0];
            float* p1 = &C[(size_t)(r0 + 8) * DMODEL + c0];
            p0[0] = rna_tf32(acc[mt][nt][0] + b0);  p0[1] = rna_tf32(acc[mt][nt][1] + b1);
            p1[0] = rna_tf32(acc[mt][nt][2] + b0);  p1[1] = rna_tf32(acc[mt][nt][3] + b1);
        }
    }
}

// v^T: g_vt[b][d][s] = g_proj_v[b][s][d]. grid (DMODEL/32, SEQ/32, BATCH), block (32,8)
__global__ void vtrans_kernel()
{
    const int b = blockIdx.z;
    const float* Vp = g_proj_v + (size_t)b * SEQ * DMODEL;
    float* VT = g_vt + (size_t)b * DMODEL * SEQ;
    __shared__ float tl[32][33];
    const int x0 = blockIdx.x * 32, y0 = blockIdx.y * 32;   // x: d, y: s
    const int tx = threadIdx.x, ty = threadIdx.y;
    #pragma unroll
    for (int r = ty; r < 32; r += 8)
        tl[r][tx] = Vp[(size_t)(y0 + r) * DMODEL + x0 + tx];
    __syncthreads();
    #pragma unroll
    for (int r = ty; r < 32; r += 8)
        VT[(size_t)(x0 + r) * SEQ + y0 + tx] = tl[tx][r];
}

// ---------------------------------------------------------------------------
// GEMM 2: scores = q.k^T/32 on lower-triangle tiles (256-wide).
// grid (SEQ/256, SEQ/128, BATCH); keep tile iff 2*jt2 <= it.
// ---------------------------------------------------------------------------
__global__ __launch_bounds__(256, 1) void scores_kernel()
{
    const int jt2 = blockIdx.x, it = blockIdx.y, b = blockIdx.z;
    if (2 * jt2 > it) return;

    extern __shared__ uint32_t sm[];
    const uint32_t smb = (uint32_t)__cvta_generic_to_shared(sm);

    const int i0 = it * 128, j0 = jt2 * 256;
    const float* q = g_proj_q + (size_t)b * SEQ * DMODEL;
    const float* k = g_proj_k + (size_t)b * SEQ * DMODEL;

    float acc[4][8][4];
    #pragma unroll
    for (int i = 0; i < 4; i++)
        #pragma unroll
        for (int j = 0; j < 8; j++)
            #pragma unroll
            for (int c = 0; c < 4; c++) acc[i][j][c] = 0.f;

    mainloop_nt(q + (size_t)i0 * DMODEL, DMODEL,
                k + (size_t)j0 * DMODEL, DMODEL,
                DMODEL / 32, smb, acc);

    float* sc = g_scores + (size_t)b * SEQ * SEQ;
    const int t = threadIdx.x, warp = t >> 5, lane = t & 31;
    const int wm = warp >> 2, wn = warp & 3;
    const int g = lane >> 2, tq = lane & 3;
    const float scale = 0.03125f;    // 1/sqrt(1024)

    #pragma unroll
    for (int mt = 0; mt < 4; mt++) {
        const int gi0 = i0 + wm * 64 + mt * 16 + g;
        #pragma unroll
        for (int nt = 0; nt < 8; nt++) {
            const int gj = j0 + wn * 64 + nt * 8 + tq * 2;
            float* p0 = &sc[(size_t)gi0 * SEQ + gj];
            float* p1 = &sc[(size_t)(gi0 + 8) * SEQ + gj];
            p0[0] = acc[mt][nt][0] * scale;  p0[1] = acc[mt][nt][1] * scale;
            p1[0] = acc[mt][nt][2] * scale;  p1[1] = acc[mt][nt][3] * scale;
        }
    }
}

// ---------------------------------------------------------------------------
// Softmax: single-read register-cached, masks by index, rounds P,
// zero-fills [len, ceil128(len)).
// ---------------------------------------------------------------------------
__global__ __launch_bounds__(256) void softmax_kernel()
{
    const int r = blockIdx.x;
    const int b = r >> 11, i = r & 2047;
    float* row = g_scores + (size_t)b * SEQ * SEQ + (size_t)i * SEQ;
    const int len = i + 1;
    const int kmax = ((i >> 7) + 1) << 7;
    const int n4 = kmax >> 2;
    const int t = threadIdx.x;

    __shared__ float red[256];

    float4 v[2];
    float mx = -3.0e38f;
    #pragma unroll
    for (int kk = 0; kk < 2; kk++) {
        const int i4 = t + kk * 256;
        if (i4 < n4) {
            v[kk] = ((const float4*)row)[i4];
            const int j = i4 * 4;
            if (j + 0 < len) mx = fmaxf(mx, v[kk].x);
            if (j + 1 < len) mx = fmaxf(mx, v[kk].y);
            if (j + 2 < len) mx = fmaxf(mx, v[kk].z);
            if (j + 3 < len) mx = fmaxf(mx, v[kk].w);
        }
    }
    red[t] = mx;
    __syncthreads();
    for (int s2 = 128; s2 > 0; s2 >>= 1) {
        if (t < s2) red[t] = fmaxf(red[t], red[t + s2]);
        __syncthreads();
    }
    mx = red[0];
    __syncthreads();

    float sum = 0.f;
    #pragma unroll
    for (int kk = 0; kk < 2; kk++) {
        const int i4 = t + kk * 256;
        if (i4 < n4) {
            const int j = i4 * 4;
            v[kk].x = (j + 0 < len) ? __expf(v[kk].x - mx) : 0.f;
            v[kk].y = (j + 1 < len) ? __expf(v[kk].y - mx) : 0.f;
            v[kk].z = (j + 2 < len) ? __expf(v[kk].z - mx) : 0.f;
            v[kk].w = (j + 3 < len) ? __expf(v[kk].w - mx) : 0.f;
            sum += v[kk].x + v[kk].y + v[kk].z + v[kk].w;
        }
    }
    red[t] = sum;
    __syncthreads();
    for (int s2 = 128; s2 > 0; s2 >>= 1) {
        if (t < s2) red[t] += red[t + s2];
        __syncthreads();
    }
    const float inv = 1.0f / red[0];

    #pragma unroll
    for (int kk = 0; kk < 2; kk++) {
        const int i4 = t + kk * 256;
        if (i4 < n4) {
            float4 o;
            o.x = rna_tf32(v[kk].x * inv);
            o.y = rna_tf32(v[kk].y * inv);
            o.z = rna_tf32(v[kk].z * inv);
            o.w = rna_tf32(v[kk].w * inv);
            ((float4*)row)[i4] = o;
        }
    }
}

// ---------------------------------------------------------------------------
// GEMM 3: out = P . v (NT with v^T), K truncated at causal boundary.
// grid = (DMODEL/256, SEQ/128, BATCH)
// ---------------------------------------------------------------------------
__global__ __launch_bounds__(256, 1) void out_kernel(float* __restrict__ Out)
{
    const int nt0 = blockIdx.x, it = blockIdx.y, b = blockIdx.z;

    extern __shared__ uint32_t sm[];
    const uint32_t smb = (uint32_t)__cvta_generic_to_shared(sm);

    const int i0 = it * 128, e0 = nt0 * 256;
    const float* P  = g_scores + (size_t)b * SEQ * SEQ;
    const float* vt = g_vt + (size_t)b * DMODEL * SEQ;

    float acc[4][8][4];
    #pragma unroll
    for (int i = 0; i < 4; i++)
        #pragma unroll
        for (int j = 0; j < 8; j++)
            #pragma unroll
            for (int c = 0; c < 4; c++) acc[i][j][c] = 0.f;

    mainloop_nt(P + (size_t)i0 * SEQ, SEQ,
                vt + (size_t)e0 * SEQ, SEQ,
                (it + 1) * 4, smb, acc);

    float* C = Out + (size_t)b * SEQ * DMODEL;
    const int t = threadIdx.x, warp = t >> 5, lane = t & 31;
    const int wm = warp >> 2, wn = warp & 3;
    const int g = lane >> 2, tq = lane & 3;

    #pragma unroll
    for (int mt = 0; mt < 4; mt++) {
        const int r0 = i0 + wm * 64 + mt * 16 + g;
        #pragma unroll
        for (int nt = 0; nt < 8; nt++) {
            const int c0 = e0 + wn * 64 + nt * 8 + tq * 2;
            float* p0 = &C[(size_t)r0 * DMODEL + c0];
            float* p1 = &C[(size_t)(r0 + 8) * DMODEL + c0];
            p0[0] = acc[mt][nt][0];  p0[1] = acc[mt][nt][1];
            p1[0] = acc[mt][nt][2];  p1[1] = acc[mt][nt][3];
        }
    }
}

// ---------------------------------------------------------------------------
// Launch. Inputs: Q, K, V, Wq, Wk, Wv, bq, bk, bv, mask (mask == tril ones).
// ---------------------------------------------------------------------------
extern "C" void kernel_launch(void* const* d_in, const int* in_sizes, int n_in,
                              void* d_out, int out_size)
{
    const float* Q  = (const float*)d_in[0];
    const float* K  = (const float*)d_in[1];
    const float* V  = (const float*)d_in[2];
    const float* Wq = (const float*)d_in[3];
    const float* Wk = (const float*)d_in[4];
    const float* Wv = (const float*)d_in[5];
    const float* bq = (const float*)d_in[6];
    const float* bk = (const float*)d_in[7];
    const float* bv = (const float*)d_in[8];
    float* Out = (float*)d_out;

    cudaFuncSetAttribute(proj_kernel,   cudaFuncAttributeMaxDynamicSharedMemorySize, SMEM_BYTES);
    cudaFuncSetAttribute(scores_kernel, cudaFuncAttributeMaxDynamicSharedMemorySize, SMEM_BYTES);
    cudaFuncSetAttribute(out_kernel,    cudaFuncAttributeMaxDynamicSharedMemorySize, SMEM_BYTES);

    round_qkv<<<2048, 256>>>(Q, K, V);
    wtrans_kernel<<<dim3(32, 32, 3), dim3(32, 8)>>>(Wq, Wk, Wv);
    proj_kernel<<<dim3(DMODEL / 256, NROWS / 128, 3), 256, SMEM_BYTES>>>(bq, bk, bv);
    vtrans_kernel<<<dim3(DMODEL / 32, SEQ / 32, BATCH), dim3(32, 8)>>>();
    scores_kernel<<<dim3(SEQ / 256, SEQ / 128, BATCH), 256, SMEM_BYTES>>>();
    softmax_kernel<<<NROWS, 256>>>();
    out_kernel<<<dim3(DMODEL / 256, SEQ / 128, BATCH), 256, SMEM_BYTES>>>(Out);
}

// round 8
// speedup vs baseline: 1.9357x; 1.9357x over previous
#include <cuda_runtime.h>
#include <cuda_fp16.h>
#include <cstdint>

// Problem dims (fixed by the reference)
#define BATCH 8
#define SEQ   2048
#define DMODEL 1024
#define NROWS (BATCH * SEQ)          // 16384

// Scratch (GEMM operands in fp16, scores in fp32, P in fp16)
__device__ __half g_rq[(size_t)NROWS * DMODEL];
__device__ __half g_rk[(size_t)NROWS * DMODEL];
__device__ __half g_rv[(size_t)NROWS * DMODEL];
__device__ __half g_wt[(size_t)3 * DMODEL * DMODEL];        // W^T fp16
__device__ __half g_q [(size_t)NROWS * DMODEL];             // projections fp16
__device__ __half g_k [(size_t)NROWS * DMODEL];
__device__ __half g_v [(size_t)NROWS * DMODEL];
__device__ __half g_vt[(size_t)BATCH * DMODEL * SEQ];       // v^T per batch
__device__ float  g_scores[(size_t)BATCH * SEQ * SEQ];      // raw scores fp32
__device__ __half g_p[(size_t)BATCH * SEQ * SEQ];           // softmax P fp16

// ---------------------------------------------------------------------------
// Helpers
// ---------------------------------------------------------------------------
__device__ __forceinline__ void mma16(float* c,
                                      uint32_t a0, uint32_t a1, uint32_t a2, uint32_t a3,
                                      uint32_t b0, uint32_t b1) {
    asm volatile(
        "mma.sync.aligned.m16n8k16.row.col.f32.f16.f16.f32 "
        "{%0,%1,%2,%3},{%4,%5,%6,%7},{%8,%9},{%0,%1,%2,%3};\n"
        : "+f"(c[0]), "+f"(c[1]), "+f"(c[2]), "+f"(c[3])
        : "r"(a0), "r"(a1), "r"(a2), "r"(a3), "r"(b0), "r"(b1));
}

__device__ __forceinline__ void ldsm4(uint32_t* r, uint32_t saddr) {
    asm volatile("ldmatrix.sync.aligned.m8n8.x4.shared.b16 {%0,%1,%2,%3}, [%4];"
        : "=r"(r[0]), "=r"(r[1]), "=r"(r[2]), "=r"(r[3]) : "r"(saddr));
}
__device__ __forceinline__ void ldsm2(uint32_t* r, uint32_t saddr) {
    asm volatile("ldmatrix.sync.aligned.m8n8.x2.shared.b16 {%0,%1}, [%2];"
        : "=r"(r[0]), "=r"(r[1]) : "r"(saddr));
}

__device__ __forceinline__ void cpa16(uint32_t saddr, const void* g) {
    asm volatile("cp.async.cg.shared.global [%0], [%1], 16;\n" :: "r"(saddr), "l"(g));
}
#define CPA_COMMIT()  asm volatile("cp.async.commit_group;\n")
#define CPA_WAIT1()   asm volatile("cp.async.wait_group 1;\n" ::: "memory")
#define CPA_WAIT0()   asm volatile("cp.async.wait_group 0;\n" ::: "memory")

// Tiles: A and B each 128 rows x 64 halves (128B payload), row stride 144B
// (= 36 u32: conflict-free for ldmatrix 8-row gathers and cp.async stores).
// 2 stages of (A + B).
#define ROWB       144
#define TILE_BYTES (128 * ROWB)          // 18432
#define STG_BYTES  (2 * TILE_BYTES)      // 36864
#define SMEM_BYTES (2 * STG_BYTES)       // 73728

// ---------------------------------------------------------------------------
// Unified NT fp16 mainloop: acc[4][4][4] += A[128,K] . B[128,K]^T
// K = T*64. 8 warps in 2x4; warp tile 64x32.
// ---------------------------------------------------------------------------
__device__ __forceinline__ void mainloop_nt(
    const __half* __restrict__ Ag, int lda,
    const __half* __restrict__ Bg, int ldb,
    int T, uint32_t smb, float acc[4][4][4])
{
    const int t = threadIdx.x;
    const int warp = t >> 5, lane = t & 31;
    const int wm = warp >> 2, wn = warp & 3;

    // ldmatrix per-lane byte offsets (relative to tile base)
    const int rowin = lane & 7;
    const int tA = lane >> 3;                      // x4: (m8, k8) tile select
    uint32_t offA[4], offB[4];
    #pragma unroll
    for (int mt = 0; mt < 4; mt++) {
        const int r = wm * 64 + mt * 16 + (tA & 1) * 8 + rowin;
        offA[mt] = (uint32_t)(r * ROWB + (tA >> 1) * 16);
    }
    const int tB = (lane >> 3) & 1;                // x2: k8 tile select
    #pragma unroll
    for (int nt = 0; nt < 4; nt++) {
        const int r = wn * 32 + nt * 8 + rowin;
        offB[nt] = (uint32_t)(r * ROWB + tB * 16);
    }

    auto issue = [&](int tt, int s) {
        const uint32_t sa = smb + s * STG_BYTES;
        const __half* ak = Ag + tt * 64;
        #pragma unroll
        for (int i = 0; i < 4; i++) {              // A: 1024 chunks / 256 thr
            const int ch = t + i * 256, r = ch >> 3, c = ch & 7;
            cpa16(sa + r * ROWB + c * 16, ak + (size_t)r * lda + c * 8);
        }
        const uint32_t sb = sa + TILE_BYTES;
        const __half* bk = Bg + tt * 64;
        #pragma unroll
        for (int i = 0; i < 4; i++) {
            const int ch = t + i * 256, r = ch >> 3, c = ch & 7;
            cpa16(sb + r * ROWB + c * 16, bk + (size_t)r * ldb + c * 8);
        }
        CPA_COMMIT();
    };

    issue(0, 0);

    for (int tt = 0; tt < T; tt++) {
        const int cur = tt & 1;
        if (tt + 1 < T) { issue(tt + 1, cur ^ 1); CPA_WAIT1(); }
        else            { CPA_WAIT0(); }
        __syncthreads();

        const uint32_t abase = smb + cur * STG_BYTES;
        const uint32_t bbase = abase + TILE_BYTES;

        #pragma unroll
        for (int ks = 0; ks < 4; ks++) {           // 4 k16-steps per 64-k tile
            const uint32_t kboff = ks * 32;        // 16 halves * 2B
            uint32_t af[4][4], bf[4][2];
            #pragma unroll
            for (int mt = 0; mt < 4; mt++) ldsm4(af[mt], abase + offA[mt] + kboff);
            #pragma unroll
            for (int nt = 0; nt < 4; nt++) ldsm2(bf[nt], bbase + offB[nt] + kboff);
            #pragma unroll
            for (int mt = 0; mt < 4; mt++)
                #pragma unroll
                for (int nt = 0; nt < 4; nt++)
                    mma16(acc[mt][nt], af[mt][0], af[mt][1], af[mt][2], af[mt][3],
                          bf[nt][0], bf[nt][1]);
        }
        __syncthreads();
    }
}

// ---------------------------------------------------------------------------
// Pre-pass 1: convert Q,K,V to fp16
// ---------------------------------------------------------------------------
__global__ __launch_bounds__(256) void round_qkv(
    const float* __restrict__ Q, const float* __restrict__ K, const float* __restrict__ V)
{
    const size_t n4 = (size_t)NROWS * DMODEL / 4;
    for (size_t i = (size_t)blockIdx.x * blockDim.x + threadIdx.x; i < n4;
         i += (size_t)gridDim.x * blockDim.x) {
        float4 a;
        a = ((const float4*)Q)[i];
        ((__half2*)g_rq)[i * 2]     = __floats2half2_rn(a.x, a.y);
        ((__half2*)g_rq)[i * 2 + 1] = __floats2half2_rn(a.z, a.w);
        a = ((const float4*)K)[i];
        ((__half2*)g_rk)[i * 2]     = __floats2half2_rn(a.x, a.y);
        ((__half2*)g_rk)[i * 2 + 1] = __floats2half2_rn(a.z, a.w);
        a = ((const float4*)V)[i];
        ((__half2*)g_rv)[i * 2]     = __floats2half2_rn(a.x, a.y);
        ((__half2*)g_rv)[i * 2 + 1] = __floats2half2_rn(a.z, a.w);
    }
}

// Pre-pass 2: W^T in fp16. grid (32,32,3), block (32,8)
__global__ void wtrans_kernel(
    const float* __restrict__ Wq, const float* __restrict__ Wk, const float* __restrict__ Wv)
{
    const int which = blockIdx.z;
    const float* W = (which == 0) ? Wq : (which == 1) ? Wk : Wv;
    __half* WT = g_wt + (size_t)which * DMODEL * DMODEL;
    __shared__ float tl[32][33];
    const int x0 = blockIdx.x * 32, y0 = blockIdx.y * 32;
    const int tx = threadIdx.x, ty = threadIdx.y;
    #pragma unroll
    for (int r = ty; r < 32; r += 8)
        tl[r][tx] = W[(size_t)(y0 + r) * DMODEL + x0 + tx];
    __syncthreads();
    #pragma unroll
    for (int r = ty; r < 32; r += 8)
        WT[(size_t)(x0 + r) * DMODEL + y0 + tx] = __float2half_rn(tl[tx][r]);
}

// ---------------------------------------------------------------------------
// GEMM 1: projections (NT with W^T). grid = (DMODEL/128, NROWS/128, 3)
// ---------------------------------------------------------------------------
__global__ __launch_bounds__(256, 2) void proj_kernel(
    const float* __restrict__ bq, const float* __restrict__ bk, const float* __restrict__ bv)
{
    const int which = blockIdx.z;
    const __half* A    = (which == 0) ? g_rq : (which == 1) ? g_rk : g_rv;
    const __half* Bw   = g_wt + (size_t)which * DMODEL * DMODEL;
    const float*  bias = (which == 0) ? bq : (which == 1) ? bk : bv;
    __half* C          = (which == 0) ? g_q : (which == 1) ? g_k : g_v;

    extern __shared__ uint32_t sm[];
    const uint32_t smb = (uint32_t)__cvta_generic_to_shared(sm);

    const int m0 = blockIdx.y * 128;
    const int n0 = blockIdx.x * 128;

    float acc[4][4][4];
    #pragma unroll
    for (int i = 0; i < 4; i++)
        #pragma unroll
        for (int j = 0; j < 4; j++)
            #pragma unroll
            for (int c = 0; c < 4; c++) acc[i][j][c] = 0.f;

    mainloop_nt(A + (size_t)m0 * DMODEL, DMODEL,
                Bw + (size_t)n0 * DMODEL, DMODEL,
                DMODEL / 64, smb, acc);

    const int t = threadIdx.x, warp = t >> 5, lane = t & 31;
    const int wm = warp >> 2, wn = warp & 3;
    const int g = lane >> 2, tq = lane & 3;

    #pragma unroll
    for (int mt = 0; mt < 4; mt++) {
        const int r0 = m0 + wm * 64 + mt * 16 + g;
        #pragma unroll
        for (int nt = 0; nt < 4; nt++) {
            const int c0 = n0 + wn * 32 + nt * 8 + tq * 2;
            const float b0 = bias[c0], b1 = bias[c0 + 1];
            *(__half2*)&C[(size_t)r0 * DMODEL + c0] =
                __floats2half2_rn(acc[mt][nt][0] + b0, acc[mt][nt][1] + b1);
            *(__half2*)&C[(size_t)(r0 + 8) * DMODEL + c0] =
                __floats2half2_rn(acc[mt][nt][2] + b0, acc[mt][nt][3] + b1);
        }
    }
}

// v^T: g_vt[b][d][s] = g_v[b][s][d]. grid (DMODEL/32, SEQ/32, BATCH), block (32,8)
__global__ void vtrans_kernel()
{
    const int b = blockIdx.z;
    const __half* Vp = g_v + (size_t)b * SEQ * DMODEL;
    __half* VT = g_vt + (size_t)b * DMODEL * SEQ;
    __shared__ __half tl[32][33];
    const int x0 = blockIdx.x * 32, y0 = blockIdx.y * 32;   // x: d, y: s
    const int tx = threadIdx.x, ty = threadIdx.y;
    #pragma unroll
    for (int r = ty; r < 32; r += 8)
        tl[r][tx] = Vp[(size_t)(y0 + r) * DMODEL + x0 + tx];
    __syncthreads();
    #pragma unroll
    for (int r = ty; r < 32; r += 8)
        VT[(size_t)(x0 + r) * SEQ + y0 + tx] = tl[tx][r];
}

// ---------------------------------------------------------------------------
// GEMM 2: scores = q.k^T/32 on lower-triangle tiles. grid (16,16,BATCH)
// ---------------------------------------------------------------------------
__global__ __launch_bounds__(256, 2) void scores_kernel()
{
    const int jt = blockIdx.x, it = blockIdx.y, b = blockIdx.z;
    if (jt > it) return;

    extern __shared__ uint32_t sm[];
    const uint32_t smb = (uint32_t)__cvta_generic_to_shared(sm);

    const int i0 = it * 128, j0 = jt * 128;
    const __half* q = g_q + (size_t)b * SEQ * DMODEL;
    const __half* k = g_k + (size_t)b * SEQ * DMODEL;

    float acc[4][4][4];
    #pragma unroll
    for (int i = 0; i < 4; i++)
        #pragma unroll
        for (int j = 0; j < 4; j++)
            #pragma unroll
            for (int c = 0; c < 4; c++) acc[i][j][c] = 0.f;

    mainloop_nt(q + (size_t)i0 * DMODEL, DMODEL,
                k + (size_t)j0 * DMODEL, DMODEL,
                DMODEL / 64, smb, acc);

    float* sc = g_scores + (size_t)b * SEQ * SEQ;
    const int t = threadIdx.x, warp = t >> 5, lane = t & 31;
    const int wm = warp >> 2, wn = warp & 3;
    const int g = lane >> 2, tq = lane & 3;
    const float scale = 0.03125f;    // 1/sqrt(1024)

    #pragma unroll
    for (int mt = 0; mt < 4; mt++) {
        const int gi0 = i0 + wm * 64 + mt * 16 + g;
        #pragma unroll
        for (int nt = 0; nt < 4; nt++) {
            const int gj = j0 + wn * 32 + nt * 8 + tq * 2;
            float* p0 = &sc[(size_t)gi0 * SEQ + gj];
            float* p1 = &sc[(size_t)(gi0 + 8) * SEQ + gj];
            p0[0] = acc[mt][nt][0] * scale;  p0[1] = acc[mt][nt][1] * scale;
            p1[0] = acc[mt][nt][2] * scale;  p1[1] = acc[mt][nt][3] * scale;
        }
    }
}

// ---------------------------------------------------------------------------
// Softmax: reads fp32 scores (single pass, register-cached), masks by index,
// writes fp16 P for j<len, zeros for [len, ceil128(len)).
// ---------------------------------------------------------------------------
__global__ __launch_bounds__(256) void softmax_kernel()
{
    const int r = blockIdx.x;
    const int b = r >> 11, i = r & 2047;
    const float* row = g_scores + (size_t)b * SEQ * SEQ + (size_t)i * SEQ;
    __half* rowp = g_p + (size_t)b * SEQ * SEQ + (size_t)i * SEQ;
    const int len = i + 1;
    const int kmax = ((i >> 7) + 1) << 7;
    const int n4 = kmax >> 2;
    const int t = threadIdx.x;

    __shared__ float red[256];

    float4 v[2];
    float mx = -3.0e38f;
    #pragma unroll
    for (int kk = 0; kk < 2; kk++) {
        const int i4 = t + kk * 256;
        if (i4 < n4) {
            v[kk] = ((const float4*)row)[i4];
            const int j = i4 * 4;
            if (j + 0 < len) mx = fmaxf(mx, v[kk].x);
            if (j + 1 < len) mx = fmaxf(mx, v[kk].y);
            if (j + 2 < len) mx = fmaxf(mx, v[kk].z);
            if (j + 3 < len) mx = fmaxf(mx, v[kk].w);
        }
    }
    red[t] = mx;
    __syncthreads();
    for (int s2 = 128; s2 > 0; s2 >>= 1) {
        if (t < s2) red[t] = fmaxf(red[t], red[t + s2]);
        __syncthreads();
    }
    mx = red[0];
    __syncthreads();

    float sum = 0.f;
    #pragma unroll
    for (int kk = 0; kk < 2; kk++) {
        const int i4 = t + kk * 256;
        if (i4 < n4) {
            const int j = i4 * 4;
            v[kk].x = (j + 0 < len) ? __expf(v[kk].x - mx) : 0.f;
            v[kk].y = (j + 1 < len) ? __expf(v[kk].y - mx) : 0.f;
            v[kk].z = (j + 2 < len) ? __expf(v[kk].z - mx) : 0.f;
            v[kk].w = (j + 3 < len) ? __expf(v[kk].w - mx) : 0.f;
            sum += v[kk].x + v[kk].y + v[kk].z + v[kk].w;
        }
    }
    red[t] = sum;
    __syncthreads();
    for (int s2 = 128; s2 > 0; s2 >>= 1) {
        if (t < s2) red[t] += red[t + s2];
        __syncthreads();
    }
    const float inv = 1.0f / red[0];

    #pragma unroll
    for (int kk = 0; kk < 2; kk++) {
        const int i4 = t + kk * 256;
        if (i4 < n4) {
            ((__half2*)rowp)[i4 * 2]     = __floats2half2_rn(v[kk].x * inv, v[kk].y * inv);
            ((__half2*)rowp)[i4 * 2 + 1] = __floats2half2_rn(v[kk].z * inv, v[kk].w * inv);
        }
    }
}

// ---------------------------------------------------------------------------
// GEMM 3: out = P . v (NT with v^T), K truncated at causal boundary.
// grid = (DMODEL/128, SEQ/128, BATCH)
// ---------------------------------------------------------------------------
__global__ __launch_bounds__(256, 2) void out_kernel(float* __restrict__ Out)
{
    const int nt0 = blockIdx.x, it = blockIdx.y, b = blockIdx.z;

    extern __shared__ uint32_t sm[];
    const uint32_t smb = (uint32_t)__cvta_generic_to_shared(sm);

    const int i0 = it * 128, e0 = nt0 * 128;
    const __half* P  = g_p + (size_t)b * SEQ * SEQ;
    const __half* vt = g_vt + (size_t)b * DMODEL * SEQ;

    float acc[4][4][4];
    #pragma unroll
    for (int i = 0; i < 4; i++)
        #pragma unroll
        for (int j = 0; j < 4; j++)
            #pragma unroll
            for (int c = 0; c < 4; c++) acc[i][j][c] = 0.f;

    mainloop_nt(P + (size_t)i0 * SEQ, SEQ,
                vt + (size_t)e0 * SEQ, SEQ,
                (it + 1) * 2, smb, acc);

    float* C = Out + (size_t)b * SEQ * DMODEL;
    const int t = threadIdx.x, warp = t >> 5, lane = t & 31;
    const int wm = warp >> 2, wn = warp & 3;
    const int g = lane >> 2, tq = lane & 3;

    #pragma unroll
    for (int mt = 0; mt < 4; mt++) {
        const int r0 = i0 + wm * 64 + mt * 16 + g;
        #pragma unroll
        for (int nt = 0; nt < 4; nt++) {
            const int c0 = e0 + wn * 32 + nt * 8 + tq * 2;
            float* p0 = &C[(size_t)r0 * DMODEL + c0];
            float* p1 = &C[(size_t)(r0 + 8) * DMODEL + c0];
            p0[0] = acc[mt][nt][0];  p0[1] = acc[mt][nt][1];
            p1[0] = acc[mt][nt][2];  p1[1] = acc[mt][nt][3];
        }
    }
}

// ---------------------------------------------------------------------------
// Launch. Inputs: Q, K, V, Wq, Wk, Wv, bq, bk, bv, mask (mask == tril ones).
// ---------------------------------------------------------------------------
extern "C" void kernel_launch(void* const* d_in, const int* in_sizes, int n_in,
                              void* d_out, int out_size)
{
    const float* Q  = (const float*)d_in[0];
    const float* K  = (const float*)d_in[1];
    const float* V  = (const float*)d_in[2];
    const float* Wq = (const float*)d_in[3];
    const float* Wk = (const float*)d_in[4];
    const float* Wv = (const float*)d_in[5];
    const float* bq = (const float*)d_in[6];
    const float* bk = (const float*)d_in[7];
    const float* bv = (const float*)d_in[8];
    float* Out = (float*)d_out;

    cudaFuncSetAttribute(proj_kernel,   cudaFuncAttributeMaxDynamicSharedMemorySize, SMEM_BYTES);
    cudaFuncSetAttribute(scores_kernel, cudaFuncAttributeMaxDynamicSharedMemorySize, SMEM_BYTES);
    cudaFuncSetAttribute(out_kernel,    cudaFuncAttributeMaxDynamicSharedMemorySize, SMEM_BYTES);

    round_qkv<<<2048, 256>>>(Q, K, V);
    wtrans_kernel<<<dim3(32, 32, 3), dim3(32, 8)>>>(Wq, Wk, Wv);
    proj_kernel<<<dim3(DMODEL / 128, NROWS / 128, 3), 256, SMEM_BYTES>>>(bq, bk, bv);
    vtrans_kernel<<<dim3(DMODEL / 32, SEQ / 32, BATCH), dim3(32, 8)>>>();
    scores_kernel<<<dim3(SEQ / 128, SEQ / 128, BATCH), 256, SMEM_BYTES>>>();
    softmax_kernel<<<NROWS, 256>>>();
    out_kernel<<<dim3(DMODEL / 128, SEQ / 128, BATCH), 256, SMEM_BYTES>>>(Out);
}

// round 9
// speedup vs baseline: 1.9494x; 1.0071x over previous
#include <cuda_runtime.h>
#include <cuda_fp16.h>
#include <cstdint>

// Problem dims (fixed by the reference)
#define BATCH 8
#define SEQ   2048
#define DMODEL 1024
#define NROWS (BATCH * SEQ)          // 16384

// Scratch (GEMM operands in fp16, scores in fp32, P in fp16)
__device__ __half g_rq[(size_t)NROWS * DMODEL];
__device__ __half g_rk[(size_t)NROWS * DMODEL];
__device__ __half g_rv[(size_t)NROWS * DMODEL];
__device__ __half g_wt[(size_t)3 * DMODEL * DMODEL];        // W^T fp16
__device__ __half g_q [(size_t)NROWS * DMODEL];             // projections fp16
__device__ __half g_k [(size_t)NROWS * DMODEL];
__device__ __half g_v [(size_t)NROWS * DMODEL];
__device__ __half g_vt[(size_t)BATCH * DMODEL * SEQ];       // v^T per batch
__device__ float  g_scores[(size_t)BATCH * SEQ * SEQ];      // raw scores fp32
__device__ __half g_p[(size_t)BATCH * SEQ * SEQ];           // softmax P fp16

// ---------------------------------------------------------------------------
// Helpers
// ---------------------------------------------------------------------------
__device__ __forceinline__ void mma16(float* c,
                                      uint32_t a0, uint32_t a1, uint32_t a2, uint32_t a3,
                                      uint32_t b0, uint32_t b1) {
    asm volatile(
        "mma.sync.aligned.m16n8k16.row.col.f32.f16.f16.f32 "
        "{%0,%1,%2,%3},{%4,%5,%6,%7},{%8,%9},{%0,%1,%2,%3};\n"
        : "+f"(c[0]), "+f"(c[1]), "+f"(c[2]), "+f"(c[3])
        : "r"(a0), "r"(a1), "r"(a2), "r"(a3), "r"(b0), "r"(b1));
}

__device__ __forceinline__ void ldsm4(uint32_t* r, uint32_t saddr) {
    asm volatile("ldmatrix.sync.aligned.m8n8.x4.shared.b16 {%0,%1,%2,%3}, [%4];"
        : "=r"(r[0]), "=r"(r[1]), "=r"(r[2]), "=r"(r[3]) : "r"(saddr));
}
__device__ __forceinline__ void ldsm2(uint32_t* r, uint32_t saddr) {
    asm volatile("ldmatrix.sync.aligned.m8n8.x2.shared.b16 {%0,%1}, [%2];"
        : "=r"(r[0]), "=r"(r[1]) : "r"(saddr));
}

__device__ __forceinline__ void cpa16(uint32_t saddr, const void* g) {
    asm volatile("cp.async.cg.shared.global [%0], [%1], 16;\n" :: "r"(saddr), "l"(g));
}
#define CPA_COMMIT()  asm volatile("cp.async.commit_group;\n")
#define CPA_WAIT1()   asm volatile("cp.async.wait_group 1;\n" ::: "memory")
#define CPA_WAIT0()   asm volatile("cp.async.wait_group 0;\n" ::: "memory")

// Tiles: A and B each 128 rows x 64 halves (128B payload), row stride 144B
// (conflict-free for ldmatrix 8-row gathers and cp.async stores).
// 3 stages of (A + B).
#define ROWB       144
#define TILE_BYTES (128 * ROWB)          // 18432
#define STG_BYTES  (2 * TILE_BYTES)      // 36864
#define SMEM_BYTES (3 * STG_BYTES)       // 110592

// ---------------------------------------------------------------------------
// Unified NT fp16 mainloop: acc[4][4][4] += A[128,K] . B[128,K]^T
// K = T*64. 8 warps in 2x4; warp tile 64x32. 3-stage ring, depth-2
// prefetch, ONE __syncthreads per k-tile.
// Ring safety: the barrier after wait_group(t) means every warp finished
// compute(t-1), so stage (t+2)%3 == (t-1)%3 may be overwritten.
// ---------------------------------------------------------------------------
__device__ __forceinline__ void mainloop_nt(
    const __half* __restrict__ Ag, int lda,
    const __half* __restrict__ Bg, int ldb,
    int T, uint32_t smb, float acc[4][4][4])
{
    const int t = threadIdx.x;
    const int warp = t >> 5, lane = t & 31;
    const int wm = warp >> 2, wn = warp & 3;

    // ldmatrix per-lane byte offsets (relative to tile base)
    const int rowin = lane & 7;
    const int tA = lane >> 3;                      // x4: (m8, k8) tile select
    uint32_t offA[4], offB[4];
    #pragma unroll
    for (int mt = 0; mt < 4; mt++) {
        const int r = wm * 64 + mt * 16 + (tA & 1) * 8 + rowin;
        offA[mt] = (uint32_t)(r * ROWB + (tA >> 1) * 16);
    }
    const int tB = (lane >> 3) & 1;                // x2: k8 tile select
    #pragma unroll
    for (int nt = 0; nt < 4; nt++) {
        const int r = wn * 32 + nt * 8 + rowin;
        offB[nt] = (uint32_t)(r * ROWB + tB * 16);
    }

    auto issue = [&](int tt) {
        const uint32_t sa = smb + (tt % 3) * STG_BYTES;
        const __half* ak = Ag + tt * 64;
        #pragma unroll
        for (int i = 0; i < 4; i++) {              // A: 1024 chunks / 256 thr
            const int ch = t + i * 256, r = ch >> 3, c = ch & 7;
            cpa16(sa + r * ROWB + c * 16, ak + (size_t)r * lda + c * 8);
        }
        const uint32_t sb = sa + TILE_BYTES;
        const __half* bk = Bg + tt * 64;
        #pragma unroll
        for (int i = 0; i < 4; i++) {
            const int ch = t + i * 256, r = ch >> 3, c = ch & 7;
            cpa16(sb + r * ROWB + c * 16, bk + (size_t)r * ldb + c * 8);
        }
        CPA_COMMIT();
    };

    issue(0);
    if (1 < T) issue(1);

    for (int tt = 0; tt < T; tt++) {
        if (tt + 1 < T) { CPA_WAIT1(); } else { CPA_WAIT0(); }
        __syncthreads();
        if (tt + 2 < T) issue(tt + 2);

        const uint32_t abase = smb + (tt % 3) * STG_BYTES;
        const uint32_t bbase = abase + TILE_BYTES;

        #pragma unroll
        for (int ks = 0; ks < 4; ks++) {           // 4 k16-steps per 64-k tile
            const uint32_t kboff = ks * 32;        // 16 halves * 2B
            uint32_t af[4][4], bf[4][2];
            #pragma unroll
            for (int mt = 0; mt < 4; mt++) ldsm4(af[mt], abase + offA[mt] + kboff);
            #pragma unroll
            for (int nt = 0; nt < 4; nt++) ldsm2(bf[nt], bbase + offB[nt] + kboff);
            #pragma unroll
            for (int mt = 0; mt < 4; mt++)
                #pragma unroll
                for (int nt = 0; nt < 4; nt++)
                    mma16(acc[mt][nt], af[mt][0], af[mt][1], af[mt][2], af[mt][3],
                          bf[nt][0], bf[nt][1]);
        }
    }
    __syncthreads();
}

// ---------------------------------------------------------------------------
// Pre-pass 1: convert Q,K,V to fp16
// ---------------------------------------------------------------------------
__global__ __launch_bounds__(256) void round_qkv(
    const float* __restrict__ Q, const float* __restrict__ K, const float* __restrict__ V)
{
    const size_t n4 = (size_t)NROWS * DMODEL / 4;
    for (size_t i = (size_t)blockIdx.x * blockDim.x + threadIdx.x; i < n4;
         i += (size_t)gridDim.x * blockDim.x) {
        float4 a;
        a = ((const float4*)Q)[i];
        ((__half2*)g_rq)[i * 2]     = __floats2half2_rn(a.x, a.y);
        ((__half2*)g_rq)[i * 2 + 1] = __floats2half2_rn(a.z, a.w);
        a = ((const float4*)K)[i];
        ((__half2*)g_rk)[i * 2]     = __floats2half2_rn(a.x, a.y);
        ((__half2*)g_rk)[i * 2 + 1] = __floats2half2_rn(a.z, a.w);
        a = ((const float4*)V)[i];
        ((__half2*)g_rv)[i * 2]     = __floats2half2_rn(a.x, a.y);
        ((__half2*)g_rv)[i * 2 + 1] = __floats2half2_rn(a.z, a.w);
    }
}

// Pre-pass 2: W^T in fp16. grid (32,32,3), block (32,8)
__global__ void wtrans_kernel(
    const float* __restrict__ Wq, const float* __restrict__ Wk, const float* __restrict__ Wv)
{
    const int which = blockIdx.z;
    const float* W = (which == 0) ? Wq : (which == 1) ? Wk : Wv;
    __half* WT = g_wt + (size_t)which * DMODEL * DMODEL;
    __shared__ float tl[32][33];
    const int x0 = blockIdx.x * 32, y0 = blockIdx.y * 32;
    const int tx = threadIdx.x, ty = threadIdx.y;
    #pragma unroll
    for (int r = ty; r < 32; r += 8)
        tl[r][tx] = W[(size_t)(y0 + r) * DMODEL + x0 + tx];
    __syncthreads();
    #pragma unroll
    for (int r = ty; r < 32; r += 8)
        WT[(size_t)(x0 + r) * DMODEL + y0 + tx] = __float2half_rn(tl[tx][r]);
}

// ---------------------------------------------------------------------------
// GEMM 1: projections (NT with W^T). grid = (DMODEL/128, NROWS/128, 3)
// ---------------------------------------------------------------------------
__global__ __launch_bounds__(256, 2) void proj_kernel(
    const float* __restrict__ bq, const float* __restrict__ bk, const float* __restrict__ bv)
{
    const int which = blockIdx.z;
    const __half* A    = (which == 0) ? g_rq : (which == 1) ? g_rk : g_rv;
    const __half* Bw   = g_wt + (size_t)which * DMODEL * DMODEL;
    const float*  bias = (which == 0) ? bq : (which == 1) ? bk : bv;
    __half* C          = (which == 0) ? g_q : (which == 1) ? g_k : g_v;

    extern __shared__ uint32_t sm[];
    const uint32_t smb = (uint32_t)__cvta_generic_to_shared(sm);

    const int m0 = blockIdx.y * 128;
    const int n0 = blockIdx.x * 128;

    float acc[4][4][4];
    #pragma unroll
    for (int i = 0; i < 4; i++)
        #pragma unroll
        for (int j = 0; j < 4; j++)
            #pragma unroll
            for (int c = 0; c < 4; c++) acc[i][j][c] = 0.f;

    mainloop_nt(A + (size_t)m0 * DMODEL, DMODEL,
                Bw + (size_t)n0 * DMODEL, DMODEL,
                DMODEL / 64, smb, acc);

    const int t = threadIdx.x, warp = t >> 5, lane = t & 31;
    const int wm = warp >> 2, wn = warp & 3;
    const int g = lane >> 2, tq = lane & 3;

    #pragma unroll
    for (int mt = 0; mt < 4; mt++) {
        const int r0 = m0 + wm * 64 + mt * 16 + g;
        #pragma unroll
        for (int nt = 0; nt < 4; nt++) {
            const int c0 = n0 + wn * 32 + nt * 8 + tq * 2;
            const float b0 = bias[c0], b1 = bias[c0 + 1];
            *(__half2*)&C[(size_t)r0 * DMODEL + c0] =
                __floats2half2_rn(acc[mt][nt][0] + b0, acc[mt][nt][1] + b1);
            *(__half2*)&C[(size_t)(r0 + 8) * DMODEL + c0] =
                __floats2half2_rn(acc[mt][nt][2] + b0, acc[mt][nt][3] + b1);
        }
    }
}

// v^T: g_vt[b][d][s] = g_v[b][s][d]. grid (DMODEL/32, SEQ/32, BATCH), block (32,8)
__global__ void vtrans_kernel()
{
    const int b = blockIdx.z;
    const __half* Vp = g_v + (size_t)b * SEQ * DMODEL;
    __half* VT = g_vt + (size_t)b * DMODEL * SEQ;
    __shared__ __half tl[32][33];
    const int x0 = blockIdx.x * 32, y0 = blockIdx.y * 32;   // x: d, y: s
    const int tx = threadIdx.x, ty = threadIdx.y;
    #pragma unroll
    for (int r = ty; r < 32; r += 8)
        tl[r][tx] = Vp[(size_t)(y0 + r) * DMODEL + x0 + tx];
    __syncthreads();
    #pragma unroll
    for (int r = ty; r < 32; r += 8)
        VT[(size_t)(x0 + r) * SEQ + y0 + tx] = tl[tx][r];
}

// ---------------------------------------------------------------------------
// GEMM 2: scores = q.k^T/32 on lower-triangle tiles. grid (16,16,BATCH)
// ---------------------------------------------------------------------------
__global__ __launch_bounds__(256, 2) void scores_kernel()
{
    const int jt = blockIdx.x, it = blockIdx.y, b = blockIdx.z;
    if (jt > it) return;

    extern __shared__ uint32_t sm[];
    const uint32_t smb = (uint32_t)__cvta_generic_to_shared(sm);

    const int i0 = it * 128, j0 = jt * 128;
    const __half* q = g_q + (size_t)b * SEQ * DMODEL;
    const __half* k = g_k + (size_t)b * SEQ * DMODEL;

    float acc[4][4][4];
    #pragma unroll
    for (int i = 0; i < 4; i++)
        #pragma unroll
        for (int j = 0; j < 4; j++)
            #pragma unroll
            for (int c = 0; c < 4; c++) acc[i][j][c] = 0.f;

    mainloop_nt(q + (size_t)i0 * DMODEL, DMODEL,
                k + (size_t)j0 * DMODEL, DMODEL,
                DMODEL / 64, smb, acc);

    float* sc = g_scores + (size_t)b * SEQ * SEQ;
    const int t = threadIdx.x, warp = t >> 5, lane = t & 31;
    const int wm = warp >> 2, wn = warp & 3;
    const int g = lane >> 2, tq = lane & 3;
    const float scale = 0.03125f;    // 1/sqrt(1024)

    #pragma unroll
    for (int mt = 0; mt < 4; mt++) {
        const int gi0 = i0 + wm * 64 + mt * 16 + g;
        #pragma unroll
        for (int nt = 0; nt < 4; nt++) {
            const int gj = j0 + wn * 32 + nt * 8 + tq * 2;
            float* p0 = &sc[(size_t)gi0 * SEQ + gj];
            float* p1 = &sc[(size_t)(gi0 + 8) * SEQ + gj];
            p0[0] = acc[mt][nt][0] * scale;  p0[1] = acc[mt][nt][1] * scale;
            p1[0] = acc[mt][nt][2] * scale;  p1[1] = acc[mt][nt][3] * scale;
        }
    }
}

// ---------------------------------------------------------------------------
// Softmax: reads fp32 scores (single pass, register-cached), masks by index,
// writes fp16 P for j<len, zeros for [len, ceil128(len)).
// ---------------------------------------------------------------------------
__global__ __launch_bounds__(256) void softmax_kernel()
{
    const int r = blockIdx.x;
    const int b = r >> 11, i = r & 2047;
    const float* row = g_scores + (size_t)b * SEQ * SEQ + (size_t)i * SEQ;
    __half* rowp = g_p + (size_t)b * SEQ * SEQ + (size_t)i * SEQ;
    const int len = i + 1;
    const int kmax = ((i >> 7) + 1) << 7;
    const int n4 = kmax >> 2;
    const int t = threadIdx.x;

    __shared__ float red[256];

    float4 v[2];
    float mx = -3.0e38f;
    #pragma unroll
    for (int kk = 0; kk < 2; kk++) {
        const int i4 = t + kk * 256;
        if (i4 < n4) {
            v[kk] = ((const float4*)row)[i4];
            const int j = i4 * 4;
            if (j + 0 < len) mx = fmaxf(mx, v[kk].x);
            if (j + 1 < len) mx = fmaxf(mx, v[kk].y);
            if (j + 2 < len) mx = fmaxf(mx, v[kk].z);
            if (j + 3 < len) mx = fmaxf(mx, v[kk].w);
        }
    }
    red[t] = mx;
    __syncthreads();
    for (int s2 = 128; s2 > 0; s2 >>= 1) {
        if (t < s2) red[t] = fmaxf(red[t], red[t + s2]);
        __syncthreads();
    }
    mx = red[0];
    __syncthreads();

    float sum = 0.f;
    #pragma unroll
    for (int kk = 0; kk < 2; kk++) {
        const int i4 = t + kk * 256;
        if (i4 < n4) {
            const int j = i4 * 4;
            v[kk].x = (j + 0 < len) ? __expf(v[kk].x - mx) : 0.f;
            v[kk].y = (j + 1 < len) ? __expf(v[kk].y - mx) : 0.f;
            v[kk].z = (j + 2 < len) ? __expf(v[kk].z - mx) : 0.f;
            v[kk].w = (j + 3 < len) ? __expf(v[kk].w - mx) : 0.f;
            sum += v[kk].x + v[kk].y + v[kk].z + v[kk].w;
        }
    }
    red[t] = sum;
    __syncthreads();
    for (int s2 = 128; s2 > 0; s2 >>= 1) {
        if (t < s2) red[t] += red[t + s2];
        __syncthreads();
    }
    const float inv = 1.0f / red[0];

    #pragma unroll
    for (int kk = 0; kk < 2; kk++) {
        const int i4 = t + kk * 256;
        if (i4 < n4) {
            ((__half2*)rowp)[i4 * 2]     = __floats2half2_rn(v[kk].x * inv, v[kk].y * inv);
            ((__half2*)rowp)[i4 * 2 + 1] = __floats2half2_rn(v[kk].z * inv, v[kk].w * inv);
        }
    }
}

// ---------------------------------------------------------------------------
// GEMM 3: out = P . v (NT with v^T), K truncated at causal boundary.
// grid = (DMODEL/128, SEQ/128, BATCH)
// ---------------------------------------------------------------------------
__global__ __launch_bounds__(256, 2) void out_kernel(float* __restrict__ Out)
{
    const int nt0 = blockIdx.x, it = blockIdx.y, b = blockIdx.z;

    extern __shared__ uint32_t sm[];
    const uint32_t smb = (uint32_t)__cvta_generic_to_shared(sm);

    const int i0 = it * 128, e0 = nt0 * 128;
    const __half* P  = g_p + (size_t)b * SEQ * SEQ;
    const __half* vt = g_vt + (size_t)b * DMODEL * SEQ;

    float acc[4][4][4];
    #pragma unroll
    for (int i = 0; i < 4; i++)
        #pragma unroll
        for (int j = 0; j < 4; j++)
            #pragma unroll
            for (int c = 0; c < 4; c++) acc[i][j][c] = 0.f;

    mainloop_nt(P + (size_t)i0 * SEQ, SEQ,
                vt + (size_t)e0 * SEQ, SEQ,
                (it + 1) * 2, smb, acc);

    float* C = Out + (size_t)b * SEQ * DMODEL;
    const int t = threadIdx.x, warp = t >> 5, lane = t & 31;
    const int wm = warp >> 2, wn = warp & 3;
    const int g = lane >> 2, tq = lane & 3;

    #pragma unroll
    for (int mt = 0; mt < 4; mt++) {
        const int r0 = i0 + wm * 64 + mt * 16 + g;
        #pragma unroll
        for (int nt = 0; nt < 4; nt++) {
            const int c0 = e0 + wn * 32 + nt * 8 + tq * 2;
            float* p0 = &C[(size_t)r0 * DMODEL + c0];
            float* p1 = &C[(size_t)(r0 + 8) * DMODEL + c0];
            p0[0] = acc[mt][nt][0];  p0[1] = acc[mt][nt][1];
            p1[0] = acc[mt][nt][2];  p1[1] = acc[mt][nt][3];
        }
    }
}

// ---------------------------------------------------------------------------
// Launch. Inputs: Q, K, V, Wq, Wk, Wv, bq, bk, bv, mask (mask == tril ones).
// ---------------------------------------------------------------------------
extern "C" void kernel_launch(void* const* d_in, const int* in_sizes, int n_in,
                              void* d_out, int out_size)
{
    const float* Q  = (const float*)d_in[0];
    const float* K  = (const float*)d_in[1];
    const float* V  = (const float*)d_in[2];
    const float* Wq = (const float*)d_in[3];
    const float* Wk = (const float*)d_in[4];
    const float* Wv = (const float*)d_in[5];
    const float* bq = (const float*)d_in[6];
    const float* bk = (const float*)d_in[7];
    const float* bv = (const float*)d_in[8];
    float* Out = (float*)d_out;

    cudaFuncSetAttribute(proj_kernel,   cudaFuncAttributeMaxDynamicSharedMemorySize, SMEM_BYTES);
    cudaFuncSetAttribute(scores_kernel, cudaFuncAttributeMaxDynamicSharedMemorySize, SMEM_BYTES);
    cudaFuncSetAttribute(out_kernel,    cudaFuncAttributeMaxDynamicSharedMemorySize, SMEM_BYTES);

    round_qkv<<<2048, 256>>>(Q, K, V);
    wtrans_kernel<<<dim3(32, 32, 3), dim3(32, 8)>>>(Wq, Wk, Wv);
    proj_kernel<<<dim3(DMODEL / 128, NROWS / 128, 3), 256, SMEM_BYTES>>>(bq, bk, bv);
    vtrans_kernel<<<dim3(DMODEL / 32, SEQ / 32, BATCH), dim3(32, 8)>>>();
    scores_kernel<<<dim3(SEQ / 128, SEQ / 128, BATCH), 256, SMEM_BYTES>>>();
    softmax_kernel<<<NROWS, 256>>>();
    out_kernel<<<dim3(DMODEL / 128, SEQ / 128, BATCH), 256, SMEM_BYTES>>>(Out);
}

// round 10
// speedup vs baseline: 1.9803x; 1.0159x over previous
#include <cuda_runtime.h>
#include <cuda_fp16.h>
#include <cstdint>

// Problem dims (fixed by the reference)
#define BATCH 8
#define SEQ   2048
#define DMODEL 1024
#define NROWS (BATCH * SEQ)          // 16384

// Scratch (GEMM operands in fp16, scores in fp32, P in fp16)
__device__ __half g_rq[(size_t)NROWS * DMODEL];
__device__ __half g_rk[(size_t)NROWS * DMODEL];
__device__ __half g_rv[(size_t)NROWS * DMODEL];
__device__ __half g_wt[(size_t)3 * DMODEL * DMODEL];        // W^T fp16
__device__ __half g_q [(size_t)NROWS * DMODEL];             // projections fp16
__device__ __half g_k [(size_t)NROWS * DMODEL];
__device__ __half g_v [(size_t)NROWS * DMODEL];
__device__ __half g_vt[(size_t)BATCH * DMODEL * SEQ];       // v^T per batch
__device__ float  g_scores[(size_t)BATCH * SEQ * SEQ];      // raw scores fp32
__device__ __half g_p[(size_t)BATCH * SEQ * SEQ];           // softmax P fp16

// ---------------------------------------------------------------------------
// Helpers
// ---------------------------------------------------------------------------
__device__ __forceinline__ void mma16(float* c,
                                      uint32_t a0, uint32_t a1, uint32_t a2, uint32_t a3,
                                      uint32_t b0, uint32_t b1) {
    asm volatile(
        "mma.sync.aligned.m16n8k16.row.col.f32.f16.f16.f32 "
        "{%0,%1,%2,%3},{%4,%5,%6,%7},{%8,%9},{%0,%1,%2,%3};\n"
        : "+f"(c[0]), "+f"(c[1]), "+f"(c[2]), "+f"(c[3])
        : "r"(a0), "r"(a1), "r"(a2), "r"(a3), "r"(b0), "r"(b1));
}

__device__ __forceinline__ void ldsm4(uint32_t* r, uint32_t saddr) {
    asm volatile("ldmatrix.sync.aligned.m8n8.x4.shared.b16 {%0,%1,%2,%3}, [%4];"
        : "=r"(r[0]), "=r"(r[1]), "=r"(r[2]), "=r"(r[3]) : "r"(saddr));
}
__device__ __forceinline__ void ldsm2(uint32_t* r, uint32_t saddr) {
    asm volatile("ldmatrix.sync.aligned.m8n8.x2.shared.b16 {%0,%1}, [%2];"
        : "=r"(r[0]), "=r"(r[1]) : "r"(saddr));
}

__device__ __forceinline__ void cpa16(uint32_t saddr, const void* g) {
    asm volatile("cp.async.cg.shared.global [%0], [%1], 16;\n" :: "r"(saddr), "l"(g));
}
#define CPA_COMMIT()  asm volatile("cp.async.commit_group;\n")
#define CPA_WAIT1()   asm volatile("cp.async.wait_group 1;\n" ::: "memory")
#define CPA_WAIT0()   asm volatile("cp.async.wait_group 0;\n" ::: "memory")

// Tiles: A and B each 128 rows x 64 halves (128B payload), row stride 144B
// (conflict-free for ldmatrix 8-row gathers and cp.async stores).
// 3 stages of (A + B).
#define ROWB       144
#define TILE_BYTES (128 * ROWB)          // 18432
#define STG_BYTES  (2 * TILE_BYTES)      // 36864
#define SMEM_BYTES (3 * STG_BYTES)       // 110592

#define NTHR 128                          // 4 warps, 2x2 grid, warp tile 64x64

// ---------------------------------------------------------------------------
// Unified NT fp16 mainloop: acc[4][8][4] += A[128,K] . B[128,K]^T
// K = T*64. 4 warps in 2x2; warp tile 64x64. 3-stage ring, depth-2
// prefetch, ONE __syncthreads per k-tile.
// ---------------------------------------------------------------------------
__device__ __forceinline__ void mainloop_nt(
    const __half* __restrict__ Ag, int lda,
    const __half* __restrict__ Bg, int ldb,
    int T, uint32_t smb, float acc[4][8][4])
{
    const int t = threadIdx.x;
    const int warp = t >> 5, lane = t & 31;
    const int wm = warp >> 1, wn = warp & 1;

    // ldmatrix per-lane byte offsets (relative to tile base)
    const int rowin = lane & 7;
    const int tA = lane >> 3;                      // x4: (m8, k8) tile select
    uint32_t offA[4], offB[8];
    #pragma unroll
    for (int mt = 0; mt < 4; mt++) {
        const int r = wm * 64 + mt * 16 + (tA & 1) * 8 + rowin;
        offA[mt] = (uint32_t)(r * ROWB + (tA >> 1) * 16);
    }
    const int tB = (lane >> 3) & 1;                // x2: k8 tile select
    #pragma unroll
    for (int nt = 0; nt < 8; nt++) {
        const int r = wn * 64 + nt * 8 + rowin;
        offB[nt] = (uint32_t)(r * ROWB + tB * 16);
    }

    auto issue = [&](int tt) {
        const uint32_t sa = smb + (tt % 3) * STG_BYTES;
        const __half* ak = Ag + tt * 64;
        #pragma unroll
        for (int i = 0; i < 8; i++) {              // A: 1024 chunks / 128 thr
            const int ch = t + i * NTHR, r = ch >> 3, c = ch & 7;
            cpa16(sa + r * ROWB + c * 16, ak + (size_t)r * lda + c * 8);
        }
        const uint32_t sb = sa + TILE_BYTES;
        const __half* bk = Bg + tt * 64;
        #pragma unroll
        for (int i = 0; i < 8; i++) {
            const int ch = t + i * NTHR, r = ch >> 3, c = ch & 7;
            cpa16(sb + r * ROWB + c * 16, bk + (size_t)r * ldb + c * 8);
        }
        CPA_COMMIT();
    };

    issue(0);
    if (1 < T) issue(1);

    for (int tt = 0; tt < T; tt++) {
        if (tt + 1 < T) { CPA_WAIT1(); } else { CPA_WAIT0(); }
        __syncthreads();
        if (tt + 2 < T) issue(tt + 2);

        const uint32_t abase = smb + (tt % 3) * STG_BYTES;
        const uint32_t bbase = abase + TILE_BYTES;

        #pragma unroll
        for (int ks = 0; ks < 4; ks++) {           // 4 k16-steps per 64-k tile
            const uint32_t kboff = ks * 32;        // 16 halves * 2B
            uint32_t af[4][4];
            #pragma unroll
            for (int mt = 0; mt < 4; mt++) ldsm4(af[mt], abase + offA[mt] + kboff);
            #pragma unroll
            for (int h = 0; h < 2; h++) {
                uint32_t bf[4][2];
                #pragma unroll
                for (int nt = 0; nt < 4; nt++)
                    ldsm2(bf[nt], bbase + offB[h * 4 + nt] + kboff);
                #pragma unroll
                for (int mt = 0; mt < 4; mt++)
                    #pragma unroll
                    for (int nt = 0; nt < 4; nt++)
                        mma16(acc[mt][h * 4 + nt],
                              af[mt][0], af[mt][1], af[mt][2], af[mt][3],
                              bf[nt][0], bf[nt][1]);
            }
        }
    }
    __syncthreads();
}

// ---------------------------------------------------------------------------
// Pre-pass 1: convert Q,K,V to fp16
// ---------------------------------------------------------------------------
__global__ __launch_bounds__(256) void round_qkv(
    const float* __restrict__ Q, const float* __restrict__ K, const float* __restrict__ V)
{
    const size_t n4 = (size_t)NROWS * DMODEL / 4;
    for (size_t i = (size_t)blockIdx.x * blockDim.x + threadIdx.x; i < n4;
         i += (size_t)gridDim.x * blockDim.x) {
        float4 a;
        a = ((const float4*)Q)[i];
        ((__half2*)g_rq)[i * 2]     = __floats2half2_rn(a.x, a.y);
        ((__half2*)g_rq)[i * 2 + 1] = __floats2half2_rn(a.z, a.w);
        a = ((const float4*)K)[i];
        ((__half2*)g_rk)[i * 2]     = __floats2half2_rn(a.x, a.y);
        ((__half2*)g_rk)[i * 2 + 1] = __floats2half2_rn(a.z, a.w);
        a = ((const float4*)V)[i];
        ((__half2*)g_rv)[i * 2]     = __floats2half2_rn(a.x, a.y);
        ((__half2*)g_rv)[i * 2 + 1] = __floats2half2_rn(a.z, a.w);
    }
}

// Pre-pass 2: W^T in fp16. grid (32,32,3), block (32,8)
__global__ void wtrans_kernel(
    const float* __restrict__ Wq, const float* __restrict__ Wk, const float* __restrict__ Wv)
{
    const int which = blockIdx.z;
    const float* W = (which == 0) ? Wq : (which == 1) ? Wk : Wv;
    __half* WT = g_wt + (size_t)which * DMODEL * DMODEL;
    __shared__ float tl[32][33];
    const int x0 = blockIdx.x * 32, y0 = blockIdx.y * 32;
    const int tx = threadIdx.x, ty = threadIdx.y;
    #pragma unroll
    for (int r = ty; r < 32; r += 8)
        tl[r][tx] = W[(size_t)(y0 + r) * DMODEL + x0 + tx];
    __syncthreads();
    #pragma unroll
    for (int r = ty; r < 32; r += 8)
        WT[(size_t)(x0 + r) * DMODEL + y0 + tx] = __float2half_rn(tl[tx][r]);
}

// ---------------------------------------------------------------------------
// GEMM 1: projections (NT with W^T). grid = (DMODEL/128, NROWS/128, 3)
// ---------------------------------------------------------------------------
__global__ __launch_bounds__(NTHR, 2) void proj_kernel(
    const float* __restrict__ bq, const float* __restrict__ bk, const float* __restrict__ bv)
{
    const int which = blockIdx.z;
    const __half* A    = (which == 0) ? g_rq : (which == 1) ? g_rk : g_rv;
    const __half* Bw   = g_wt + (size_t)which * DMODEL * DMODEL;
    const float*  bias = (which == 0) ? bq : (which == 1) ? bk : bv;
    __half* C          = (which == 0) ? g_q : (which == 1) ? g_k : g_v;

    extern __shared__ uint32_t sm[];
    const uint32_t smb = (uint32_t)__cvta_generic_to_shared(sm);

    const int m0 = blockIdx.y * 128;
    const int n0 = blockIdx.x * 128;

    float acc[4][8][4];
    #pragma unroll
    for (int i = 0; i < 4; i++)
        #pragma unroll
        for (int j = 0; j < 8; j++)
            #pragma unroll
            for (int c = 0; c < 4; c++) acc[i][j][c] = 0.f;

    mainloop_nt(A + (size_t)m0 * DMODEL, DMODEL,
                Bw + (size_t)n0 * DMODEL, DMODEL,
                DMODEL / 64, smb, acc);

    const int t = threadIdx.x, warp = t >> 5, lane = t & 31;
    const int wm = warp >> 1, wn = warp & 1;
    const int g = lane >> 2, tq = lane & 3;

    #pragma unroll
    for (int mt = 0; mt < 4; mt++) {
        const int r0 = m0 + wm * 64 + mt * 16 + g;
        #pragma unroll
        for (int nt = 0; nt < 8; nt++) {
            const int c0 = n0 + wn * 64 + nt * 8 + tq * 2;
            const float b0 = bias[c0], b1 = bias[c0 + 1];
            *(__half2*)&C[(size_t)r0 * DMODEL + c0] =
                __floats2half2_rn(acc[mt][nt][0] + b0, acc[mt][nt][1] + b1);
            *(__half2*)&C[(size_t)(r0 + 8) * DMODEL + c0] =
                __floats2half2_rn(acc[mt][nt][2] + b0, acc[mt][nt][3] + b1);
        }
    }
}

// v^T: g_vt[b][d][s] = g_v[b][s][d]. grid (DMODEL/32, SEQ/32, BATCH), block (32,8)
__global__ void vtrans_kernel()
{
    const int b = blockIdx.z;
    const __half* Vp = g_v + (size_t)b * SEQ * DMODEL;
    __half* VT = g_vt + (size_t)b * DMODEL * SEQ;
    __shared__ __half tl[32][33];
    const int x0 = blockIdx.x * 32, y0 = blockIdx.y * 32;   // x: d, y: s
    const int tx = threadIdx.x, ty = threadIdx.y;
    #pragma unroll
    for (int r = ty; r < 32; r += 8)
        tl[r][tx] = Vp[(size_t)(y0 + r) * DMODEL + x0 + tx];
    __syncthreads();
    #pragma unroll
    for (int r = ty; r < 32; r += 8)
        VT[(size_t)(x0 + r) * SEQ + y0 + tx] = tl[tx][r];
}

// ---------------------------------------------------------------------------
// GEMM 2: scores = q.k^T/32 on lower-triangle tiles. grid (16,16,BATCH)
// ---------------------------------------------------------------------------
__global__ __launch_bounds__(NTHR, 2) void scores_kernel()
{
    const int jt = blockIdx.x, it = blockIdx.y, b = blockIdx.z;
    if (jt > it) return;

    extern __shared__ uint32_t sm[];
    const uint32_t smb = (uint32_t)__cvta_generic_to_shared(sm);

    const int i0 = it * 128, j0 = jt * 128;
    const __half* q = g_q + (size_t)b * SEQ * DMODEL;
    const __half* k = g_k + (size_t)b * SEQ * DMODEL;

    float acc[4][8][4];
    #pragma unroll
    for (int i = 0; i < 4; i++)
        #pragma unroll
        for (int j = 0; j < 8; j++)
            #pragma unroll
            for (int c = 0; c < 4; c++) acc[i][j][c] = 0.f;

    mainloop_nt(q + (size_t)i0 * DMODEL, DMODEL,
                k + (size_t)j0 * DMODEL, DMODEL,
                DMODEL / 64, smb, acc);

    float* sc = g_scores + (size_t)b * SEQ * SEQ;
    const int t = threadIdx.x, warp = t >> 5, lane = t & 31;
    const int wm = warp >> 1, wn = warp & 1;
    const int g = lane >> 2, tq = lane & 3;
    const float scale = 0.03125f;    // 1/sqrt(1024)

    #pragma unroll
    for (int mt = 0; mt < 4; mt++) {
        const int gi0 = i0 + wm * 64 + mt * 16 + g;
        #pragma unroll
        for (int nt = 0; nt < 8; nt++) {
            const int gj = j0 + wn * 64 + nt * 8 + tq * 2;
            float* p0 = &sc[(size_t)gi0 * SEQ + gj];
            float* p1 = &sc[(size_t)(gi0 + 8) * SEQ + gj];
            p0[0] = acc[mt][nt][0] * scale;  p0[1] = acc[mt][nt][1] * scale;
            p1[0] = acc[mt][nt][2] * scale;  p1[1] = acc[mt][nt][3] * scale;
        }
    }
}

// ---------------------------------------------------------------------------
// Softmax: reads fp32 scores (single pass, register-cached), masks by index,
// writes fp16 P for j<len, zeros for [len, ceil128(len)).
// ---------------------------------------------------------------------------
__global__ __launch_bounds__(256) void softmax_kernel()
{
    const int r = blockIdx.x;
    const int b = r >> 11, i = r & 2047;
    const float* row = g_scores + (size_t)b * SEQ * SEQ + (size_t)i * SEQ;
    __half* rowp = g_p + (size_t)b * SEQ * SEQ + (size_t)i * SEQ;
    const int len = i + 1;
    const int kmax = ((i >> 7) + 1) << 7;
    const int n4 = kmax >> 2;
    const int t = threadIdx.x;

    __shared__ float red[256];

    float4 v[2];
    float mx = -3.0e38f;
    #pragma unroll
    for (int kk = 0; kk < 2; kk++) {
        const int i4 = t + kk * 256;
        if (i4 < n4) {
            v[kk] = ((const float4*)row)[i4];
            const int j = i4 * 4;
            if (j + 0 < len) mx = fmaxf(mx, v[kk].x);
            if (j + 1 < len) mx = fmaxf(mx, v[kk].y);
            if (j + 2 < len) mx = fmaxf(mx, v[kk].z);
            if (j + 3 < len) mx = fmaxf(mx, v[kk].w);
        }
    }
    red[t] = mx;
    __syncthreads();
    for (int s2 = 128; s2 > 0; s2 >>= 1) {
        if (t < s2) red[t] = fmaxf(red[t], red[t + s2]);
        __syncthreads();
    }
    mx = red[0];
    __syncthreads();

    float sum = 0.f;
    #pragma unroll
    for (int kk = 0; kk < 2; kk++) {
        const int i4 = t + kk * 256;
        if (i4 < n4) {
            const int j = i4 * 4;
            v[kk].x = (j + 0 < len) ? __expf(v[kk].x - mx) : 0.f;
            v[kk].y = (j + 1 < len) ? __expf(v[kk].y - mx) : 0.f;
            v[kk].z = (j + 2 < len) ? __expf(v[kk].z - mx) : 0.f;
            v[kk].w = (j + 3 < len) ? __expf(v[kk].w - mx) : 0.f;
            sum += v[kk].x + v[kk].y + v[kk].z + v[kk].w;
        }
    }
    red[t] = sum;
    __syncthreads();
    for (int s2 = 128; s2 > 0; s2 >>= 1) {
        if (t < s2) red[t] += red[t + s2];
        __syncthreads();
    }
    const float inv = 1.0f / red[0];

    #pragma unroll
    for (int kk = 0; kk < 2; kk++) {
        const int i4 = t + kk * 256;
        if (i4 < n4) {
            ((__half2*)rowp)[i4 * 2]     = __floats2half2_rn(v[kk].x * inv, v[kk].y * inv);
            ((__half2*)rowp)[i4 * 2 + 1] = __floats2half2_rn(v[kk].z * inv, v[kk].w * inv);
        }
    }
}

// ---------------------------------------------------------------------------
// GEMM 3: out = P . v (NT with v^T), K truncated at causal boundary.
// grid = (DMODEL/128, SEQ/128, BATCH)
// ---------------------------------------------------------------------------
__global__ __launch_bounds__(NTHR, 2) void out_kernel(float* __restrict__ Out)
{
    const int nt0 = blockIdx.x, it = blockIdx.y, b = blockIdx.z;

    extern __shared__ uint32_t sm[];
    const uint32_t smb = (uint32_t)__cvta_generic_to_shared(sm);

    const int i0 = it * 128, e0 = nt0 * 128;
    const __half* P  = g_p + (size_t)b * SEQ * SEQ;
    const __half* vt = g_vt + (size_t)b * DMODEL * SEQ;

    float acc[4][8][4];
    #pragma unroll
    for (int i = 0; i < 4; i++)
        #pragma unroll
        for (int j = 0; j < 8; j++)
            #pragma unroll
            for (int c = 0; c < 4; c++) acc[i][j][c] = 0.f;

    mainloop_nt(P + (size_t)i0 * SEQ, SEQ,
                vt + (size_t)e0 * SEQ, SEQ,
                (it + 1) * 2, smb, acc);

    float* C = Out + (size_t)b * SEQ * DMODEL;
    const int t = threadIdx.x, warp = t >> 5, lane = t & 31;
    const int wm = warp >> 1, wn = warp & 1;
    const int g = lane >> 2, tq = lane & 3;

    #pragma unroll
    for (int mt = 0; mt < 4; mt++) {
        const int r0 = i0 + wm * 64 + mt * 16 + g;
        #pragma unroll
        for (int nt = 0; nt < 8; nt++) {
            const int c0 = e0 + wn * 64 + nt * 8 + tq * 2;
            float* p0 = &C[(size_t)r0 * DMODEL + c0];
            float* p1 = &C[(size_t)(r0 + 8) * DMODEL + c0];
            p0[0] = acc[mt][nt][0];  p0[1] = acc[mt][nt][1];
            p1[0] = acc[mt][nt][2];  p1[1] = acc[mt][nt][3];
        }
    }
}

// ---------------------------------------------------------------------------
// Launch. Inputs: Q, K, V, Wq, Wk, Wv, bq, bk, bv, mask (mask == tril ones).
// ---------------------------------------------------------------------------
extern "C" void kernel_launch(void* const* d_in, const int* in_sizes, int n_in,
                              void* d_out, int out_size)
{
    const float* Q  = (const float*)d_in[0];
    const float* K  = (const float*)d_in[1];
    const float* V  = (const float*)d_in[2];
    const float* Wq = (const float*)d_in[3];
    const float* Wk = (const float*)d_in[4];
    const float* Wv = (const float*)d_in[5];
    const float* bq = (const float*)d_in[6];
    const float* bk = (const float*)d_in[7];
    const float* bv = (const float*)d_in[8];
    float* Out = (float*)d_out;

    cudaFuncSetAttribute(proj_kernel,   cudaFuncAttributeMaxDynamicSharedMemorySize, SMEM_BYTES);
    cudaFuncSetAttribute(scores_kernel, cudaFuncAttributeMaxDynamicSharedMemorySize, SMEM_BYTES);
    cudaFuncSetAttribute(out_kernel,    cudaFuncAttributeMaxDynamicSharedMemorySize, SMEM_BYTES);

    round_qkv<<<2048, 256>>>(Q, K, V);
    wtrans_kernel<<<dim3(32, 32, 3), dim3(32, 8)>>>(Wq, Wk, Wv);
    proj_kernel<<<dim3(DMODEL / 128, NROWS / 128, 3), NTHR, SMEM_BYTES>>>(bq, bk, bv);
    vtrans_kernel<<<dim3(DMODEL / 32, SEQ / 32, BATCH), dim3(32, 8)>>>();
    scores_kernel<<<dim3(SEQ / 128, SEQ / 128, BATCH), NTHR, SMEM_BYTES>>>();
    softmax_kernel<<<NROWS, 256>>>();
    out_kernel<<<dim3(DMODEL / 128, SEQ / 128, BATCH), NTHR, SMEM_BYTES>>>(Out);
}

// round 12
// speedup vs baseline: 2.0407x; 1.0305x over previous
#include <cuda_runtime.h>
#include <cuda_fp16.h>
#include <cstdint>

// Problem dims (fixed by the reference)
#define BATCH 8
#define SEQ   2048
#define DMODEL 1024
#define NROWS (BATCH * SEQ)          // 16384

// Scratch (GEMM operands in fp16, scores in fp32, P in fp16)
__device__ __half g_rq[(size_t)NROWS * DMODEL];
__device__ __half g_rk[(size_t)NROWS * DMODEL];
__device__ __half g_rv[(size_t)NROWS * DMODEL];
__device__ __half g_wt[(size_t)3 * DMODEL * DMODEL];        // W^T fp16
__device__ __half g_q [(size_t)NROWS * DMODEL];             // q/32 fp16
__device__ __half g_k [(size_t)NROWS * DMODEL];
__device__ __half g_vt[(size_t)BATCH * DMODEL * SEQ];       // v^T per batch
__device__ float  g_scores[(size_t)BATCH * SEQ * SEQ];      // raw scores fp32
__device__ __half g_p[(size_t)BATCH * SEQ * SEQ];           // softmax P fp16

// ---------------------------------------------------------------------------
// Helpers
// ---------------------------------------------------------------------------
__device__ __forceinline__ void mma16(float* c,
                                      uint32_t a0, uint32_t a1, uint32_t a2, uint32_t a3,
                                      uint32_t b0, uint32_t b1) {
    asm volatile(
        "mma.sync.aligned.m16n8k16.row.col.f32.f16.f16.f32 "
        "{%0,%1,%2,%3},{%4,%5,%6,%7},{%8,%9},{%0,%1,%2,%3};\n"
        : "+f"(c[0]), "+f"(c[1]), "+f"(c[2]), "+f"(c[3])
        : "r"(a0), "r"(a1), "r"(a2), "r"(a3), "r"(b0), "r"(b1));
}

__device__ __forceinline__ void ldsm4(uint32_t* r, uint32_t saddr) {
    asm volatile("ldmatrix.sync.aligned.m8n8.x4.shared.b16 {%0,%1,%2,%3}, [%4];"
        : "=r"(r[0]), "=r"(r[1]), "=r"(r[2]), "=r"(r[3]) : "r"(saddr));
}
__device__ __forceinline__ void ldsm2(uint32_t* r, uint32_t saddr) {
    asm volatile("ldmatrix.sync.aligned.m8n8.x2.shared.b16 {%0,%1}, [%2];"
        : "=r"(r[0]), "=r"(r[1]) : "r"(saddr));
}

__device__ __forceinline__ void cpa16(uint32_t saddr, const void* g) {
    asm volatile("cp.async.cg.shared.global [%0], [%1], 16;\n" :: "r"(saddr), "l"(g));
}
#define CPA_COMMIT()  asm volatile("cp.async.commit_group;\n")
#define CPA_WAIT1()   asm volatile("cp.async.wait_group 1;\n" ::: "memory")
#define CPA_WAIT0()   asm volatile("cp.async.wait_group 0;\n" ::: "memory")

// Tiles: A and B each 128 rows x 64 halves (128B payload), row stride 144B
// (conflict-free for ldmatrix 8-row gathers and cp.async stores).
// 3 stages of (A + B).
#define ROWB       144
#define TILE_BYTES (128 * ROWB)          // 18432
#define STG_BYTES  (2 * TILE_BYTES)      // 36864
#define SMEM_BYTES (3 * STG_BYTES)       // 110592

#define NTHR 128                          // 4 warps, 2x2 grid, warp tile 64x64

// ---------------------------------------------------------------------------
// Unified NT fp16 mainloop: acc[4][8][4] += A[128,K] . B[128,K]^T
// K = T*64. 4 warps in 2x2; warp tile 64x64. 3-stage ring, depth-2
// prefetch, ONE __syncthreads per k-tile.
// ---------------------------------------------------------------------------
__device__ __forceinline__ void mainloop_nt(
    const __half* __restrict__ Ag, int lda,
    const __half* __restrict__ Bg, int ldb,
    int T, uint32_t smb, float acc[4][8][4])
{
    const int t = threadIdx.x;
    const int warp = t >> 5, lane = t & 31;
    const int wm = warp >> 1, wn = warp & 1;

    // ldmatrix per-lane byte offsets (relative to tile base)
    const int rowin = lane & 7;
    const int tA = lane >> 3;                      // x4: (m8, k8) tile select
    uint32_t offA[4], offB[8];
    #pragma unroll
    for (int mt = 0; mt < 4; mt++) {
        const int r = wm * 64 + mt * 16 + (tA & 1) * 8 + rowin;
        offA[mt] = (uint32_t)(r * ROWB + (tA >> 1) * 16);
    }
    const int tB = (lane >> 3) & 1;                // x2: k8 tile select
    #pragma unroll
    for (int nt = 0; nt < 8; nt++) {
        const int r = wn * 64 + nt * 8 + rowin;
        offB[nt] = (uint32_t)(r * ROWB + tB * 16);
    }

    auto issue = [&](int tt) {
        const uint32_t sa = smb + (tt % 3) * STG_BYTES;
        const __half* ak = Ag + tt * 64;
        #pragma unroll
        for (int i = 0; i < 8; i++) {              // A: 1024 chunks / 128 thr
            const int ch = t + i * NTHR, r = ch >> 3, c = ch & 7;
            cpa16(sa + r * ROWB + c * 16, ak + (size_t)r * lda + c * 8);
        }
        const uint32_t sb = sa + TILE_BYTES;
        const __half* bk = Bg + tt * 64;
        #pragma unroll
        for (int i = 0; i < 8; i++) {
            const int ch = t + i * NTHR, r = ch >> 3, c = ch & 7;
            cpa16(sb + r * ROWB + c * 16, bk + (size_t)r * ldb + c * 8);
        }
        CPA_COMMIT();
    };

    issue(0);
    if (1 < T) issue(1);

    for (int tt = 0; tt < T; tt++) {
        if (tt + 1 < T) { CPA_WAIT1(); } else { CPA_WAIT0(); }
        __syncthreads();
        if (tt + 2 < T) issue(tt + 2);

        const uint32_t abase = smb + (tt % 3) * STG_BYTES;
        const uint32_t bbase = abase + TILE_BYTES;

        #pragma unroll
        for (int ks = 0; ks < 4; ks++) {           // 4 k16-steps per 64-k tile
            const uint32_t kboff = ks * 32;        // 16 halves * 2B
            uint32_t af[4][4];
            #pragma unroll
            for (int mt = 0; mt < 4; mt++) ldsm4(af[mt], abase + offA[mt] + kboff);
            #pragma unroll
            for (int h = 0; h < 2; h++) {
                uint32_t bf[4][2];
                #pragma unroll
                for (int nt = 0; nt < 4; nt++)
                    ldsm2(bf[nt], bbase + offB[h * 4 + nt] + kboff);
                #pragma unroll
                for (int mt = 0; mt < 4; mt++)
                    #pragma unroll
                    for (int nt = 0; nt < 4; nt++)
                        mma16(acc[mt][h * 4 + nt],
                              af[mt][0], af[mt][1], af[mt][2], af[mt][3],
                              bf[nt][0], bf[nt][1]);
            }
        }
    }
    __syncthreads();
}

// ---------------------------------------------------------------------------
// Pre-pass 1: convert Q,K,V to fp16
// ---------------------------------------------------------------------------
__global__ __launch_bounds__(256) void round_qkv(
    const float* __restrict__ Q, const float* __restrict__ K, const float* __restrict__ V)
{
    const size_t n4 = (size_t)NROWS * DMODEL / 4;
    for (size_t i = (size_t)blockIdx.x * blockDim.x + threadIdx.x; i < n4;
         i += (size_t)gridDim.x * blockDim.x) {
        float4 a;
        a = ((const float4*)Q)[i];
        ((__half2*)g_rq)[i * 2]     = __floats2half2_rn(a.x, a.y);
        ((__half2*)g_rq)[i * 2 + 1] = __floats2half2_rn(a.z, a.w);
        a = ((const float4*)K)[i];
        ((__half2*)g_rk)[i * 2]     = __floats2half2_rn(a.x, a.y);
        ((__half2*)g_rk)[i * 2 + 1] = __floats2half2_rn(a.z, a.w);
        a = ((const float4*)V)[i];
        ((__half2*)g_rv)[i * 2]     = __floats2half2_rn(a.x, a.y);
        ((__half2*)g_rv)[i * 2 + 1] = __floats2half2_rn(a.z, a.w);
    }
}

// Pre-pass 2: W^T in fp16. grid (32,32,3), block (32,8)
__global__ void wtrans_kernel(
    const float* __restrict__ Wq, const float* __restrict__ Wk, const float* __restrict__ Wv)
{
    const int which = blockIdx.z;
    const float* W = (which == 0) ? Wq : (which == 1) ? Wk : Wv;
    __half* WT = g_wt + (size_t)which * DMODEL * DMODEL;
    __shared__ float tl[32][33];
    const int x0 = blockIdx.x * 32, y0 = blockIdx.y * 32;
    const int tx = threadIdx.x, ty = threadIdx.y;
    #pragma unroll
    for (int r = ty; r < 32; r += 8)
        tl[r][tx] = W[(size_t)(y0 + r) * DMODEL + x0 + tx];
    __syncthreads();
    #pragma unroll
    for (int r = ty; r < 32; r += 8)
        WT[(size_t)(x0 + r) * DMODEL + y0 + tx] = __float2half_rn(tl[tx][r]);
}

// ---------------------------------------------------------------------------
// GEMM 1: projections (NT with W^T). grid = (DMODEL/128, NROWS/128, 3)
// which==0: writes q/32 (exact power-of-2 scale; commutes with fp16 rounding)
// which==2: writes V TRANSPOSED into g_vt via smem bounce (vtrans fused).
// ---------------------------------------------------------------------------
__global__ __launch_bounds__(NTHR, 2) void proj_kernel(
    const float* __restrict__ bq, const float* __restrict__ bk, const float* __restrict__ bv)
{
    const int which = blockIdx.z;
    const __half* A    = (which == 0) ? g_rq : (which == 1) ? g_rk : g_rv;
    const __half* Bw   = g_wt + (size_t)which * DMODEL * DMODEL;
    const float*  bias = (which == 0) ? bq : (which == 1) ? bk : bv;

    extern __shared__ uint32_t sm[];
    const uint32_t smb = (uint32_t)__cvta_generic_to_shared(sm);

    const int m0 = blockIdx.y * 128;
    const int n0 = blockIdx.x * 128;

    float acc[4][8][4];
    #pragma unroll
    for (int i = 0; i < 4; i++)
        #pragma unroll
        for (int j = 0; j < 8; j++)
            #pragma unroll
            for (int c = 0; c < 4; c++) acc[i][j][c] = 0.f;

    mainloop_nt(A + (size_t)m0 * DMODEL, DMODEL,
                Bw + (size_t)n0 * DMODEL, DMODEL,
                DMODEL / 64, smb, acc);

    const int t = threadIdx.x, warp = t >> 5, lane = t & 31;
    const int wm = warp >> 1, wn = warp & 1;
    const int g = lane >> 2, tq = lane & 3;

    if (which < 2) {
        __half* C = (which == 0) ? g_q : g_k;
        const float scl = (which == 0) ? 0.03125f : 1.0f;   // 1/sqrt(1024) folded into q
        #pragma unroll
        for (int mt = 0; mt < 4; mt++) {
            const int r0 = m0 + wm * 64 + mt * 16 + g;
            #pragma unroll
            for (int nt = 0; nt < 8; nt++) {
                const int c0 = n0 + wn * 64 + nt * 8 + tq * 2;
                const float b0 = bias[c0], b1 = bias[c0 + 1];
                *(__half2*)&C[(size_t)r0 * DMODEL + c0] =
                    __floats2half2_rn((acc[mt][nt][0] + b0) * scl, (acc[mt][nt][1] + b1) * scl);
                *(__half2*)&C[(size_t)(r0 + 8) * DMODEL + c0] =
                    __floats2half2_rn((acc[mt][nt][2] + b0) * scl, (acc[mt][nt][3] + b1) * scl);
            }
        }
    } else {
        // V: stage fp16 tile [row s][col e] (stride 134 halves), then write
        // g_vt[e][s] coalesced: warp = 32 consecutive half2 = 128B per e-row.
        __half* S = (__half*)sm;    // mainloop done (ends with __syncthreads)
        const int VS = 134;
        #pragma unroll
        for (int mt = 0; mt < 4; mt++) {
            const int r = wm * 64 + mt * 16 + g;
            #pragma unroll
            for (int nt = 0; nt < 8; nt++) {
                const int c = wn * 64 + nt * 8 + tq * 2;
                const float b0 = bias[n0 + c], b1 = bias[n0 + c + 1];
                *(__half2*)&S[(size_t)r * VS + c] =
                    __floats2half2_rn(acc[mt][nt][0] + b0, acc[mt][nt][1] + b1);
                *(__half2*)&S[(size_t)(r + 8) * VS + c] =
                    __floats2half2_rn(acc[mt][nt][2] + b0, acc[mt][nt][3] + b1);
            }
        }
        __syncthreads();
        const int b = m0 >> 11;          // batch
        const int s0 = m0 & 2047;        // sequence offset
        __half* vt = g_vt + (size_t)b * DMODEL * SEQ;
        const int sidx  = (t & 63) * 2;  // 0..126: s-pair handled by this thread
        const int ehalf = t >> 6;        // 0/1: which e of each pair
        #pragma unroll 4
        for (int eo = 0; eo < 64; eo++) {
            const int e = eo * 2 + ehalf;
            __half lo = S[(size_t)sidx * VS + e];
            __half hi = S[(size_t)(sidx + 1) * VS + e];
            *(__half2*)&vt[(size_t)(n0 + e) * SEQ + s0 + sidx] = __halves2half2(lo, hi);
        }
    }
}

// ---------------------------------------------------------------------------
// GEMM 2: scores = (q/32).k^T on lower-triangle tiles. grid (16,16,BATCH)
// ---------------------------------------------------------------------------
__global__ __launch_bounds__(NTHR, 2) void scores_kernel()
{
    const int jt = blockIdx.x, it = blockIdx.y, b = blockIdx.z;
    if (jt > it) return;

    extern __shared__ uint32_t sm[];
    const uint32_t smb = (uint32_t)__cvta_generic_to_shared(sm);

    const int i0 = it * 128, j0 = jt * 128;
    const __half* q = g_q + (size_t)b * SEQ * DMODEL;
    const __half* k = g_k + (size_t)b * SEQ * DMODEL;

    float acc[4][8][4];
    #pragma unroll
    for (int i = 0; i < 4; i++)
        #pragma unroll
        for (int j = 0; j < 8; j++)
            #pragma unroll
            for (int c = 0; c < 4; c++) acc[i][j][c] = 0.f;

    mainloop_nt(q + (size_t)i0 * DMODEL, DMODEL,
                k + (size_t)j0 * DMODEL, DMODEL,
                DMODEL / 64, smb, acc);

    float* sc = g_scores + (size_t)b * SEQ * SEQ;
    const int t = threadIdx.x, warp = t >> 5, lane = t & 31;
    const int wm = warp >> 1, wn = warp & 1;
    const int g = lane >> 2, tq = lane & 3;

    #pragma unroll
    for (int mt = 0; mt < 4; mt++) {
        const int gi0 = i0 + wm * 64 + mt * 16 + g;
        #pragma unroll
        for (int nt = 0; nt < 8; nt++) {
            const int gj = j0 + wn * 64 + nt * 8 + tq * 2;
            float* p0 = &sc[(size_t)gi0 * SEQ + gj];
            float* p1 = &sc[(size_t)(gi0 + 8) * SEQ + gj];
            p0[0] = acc[mt][nt][0];  p0[1] = acc[mt][nt][1];
            p1[0] = acc[mt][nt][2];  p1[1] = acc[mt][nt][3];
        }
    }
}

// ---------------------------------------------------------------------------
// Softmax: reads fp32 scores (single pass, register-cached), masks by index,
// writes fp16 P for j<len, zeros for [len, ceil128(len)).
// ---------------------------------------------------------------------------
__global__ __launch_bounds__(256) void softmax_kernel()
{
    const int r = blockIdx.x;
    const int b = r >> 11, i = r & 2047;
    const float* row = g_scores + (size_t)b * SEQ * SEQ + (size_t)i * SEQ;
    __half* rowp = g_p + (size_t)b * SEQ * SEQ + (size_t)i * SEQ;
    const int len = i + 1;
    const int kmax = ((i >> 7) + 1) << 7;
    const int n4 = kmax >> 2;
    const int t = threadIdx.x;

    __shared__ float red[256];

    float4 v[2];
    float mx = -3.0e38f;
    #pragma unroll
    for (int kk = 0; kk < 2; kk++) {
        const int i4 = t + kk * 256;
        if (i4 < n4) {
            v[kk] = ((const float4*)row)[i4];
            const int j = i4 * 4;
            if (j + 0 < len) mx = fmaxf(mx, v[kk].x);
            if (j + 1 < len) mx = fmaxf(mx, v[kk].y);
            if (j + 2 < len) mx = fmaxf(mx, v[kk].z);
            if (j + 3 < len) mx = fmaxf(mx, v[kk].w);
        }
    }
    red[t] = mx;
    __syncthreads();
    for (int s2 = 128; s2 > 0; s2 >>= 1) {
        if (t < s2) red[t] = fmaxf(red[t], red[t + s2]);
        __syncthreads();
    }
    mx = red[0];
    __syncthreads();

    float sum = 0.f;
    #pragma unroll
    for (int kk = 0; kk < 2; kk++) {
        const int i4 = t + kk * 256;
        if (i4 < n4) {
            const int j = i4 * 4;
            v[kk].x = (j + 0 < len) ? __expf(v[kk].x - mx) : 0.f;
            v[kk].y = (j + 1 < len) ? __expf(v[kk].y - mx) : 0.f;
            v[kk].z = (j + 2 < len) ? __expf(v[kk].z - mx) : 0.f;
            v[kk].w = (j + 3 < len) ? __expf(v[kk].w - mx) : 0.f;
            sum += v[kk].x + v[kk].y + v[kk].z + v[kk].w;
        }
    }
    red[t] = sum;
    __syncthreads();
    for (int s2 = 128; s2 > 0; s2 >>= 1) {
        if (t < s2) red[t] += red[t + s2];
        __syncthreads();
    }
    const float inv = 1.0f / red[0];

    #pragma unroll
    for (int kk = 0; kk < 2; kk++) {
        const int i4 = t + kk * 256;
        if (i4 < n4) {
            ((__half2*)rowp)[i4 * 2]     = __floats2half2_rn(v[kk].x * inv, v[kk].y * inv);
            ((__half2*)rowp)[i4 * 2 + 1] = __floats2half2_rn(v[kk].z * inv, v[kk].w * inv);
        }
    }
}

// ---------------------------------------------------------------------------
// GEMM 3: out = P . v (NT with v^T), K truncated at causal boundary.
// grid = (DMODEL/128, SEQ/128, BATCH)
// ---------------------------------------------------------------------------
__global__ __launch_bounds__(NTHR, 2) void out_kernel(float* __restrict__ Out)
{
    const int nt0 = blockIdx.x, it = blockIdx.y, b = blockIdx.z;

    extern __shared__ uint32_t sm[];
    const uint32_t smb = (uint32_t)__cvta_generic_to_shared(sm);

    const int i0 = it * 128, e0 = nt0 * 128;
    const __half* P  = g_p + (size_t)b * SEQ * SEQ;
    const __half* vt = g_vt + (size_t)b * DMODEL * SEQ;

    float acc[4][8][4];
    #pragma unroll
    for (int i = 0; i < 4; i++)
        #pragma unroll
        for (int j = 0; j < 8; j++)
            #pragma unroll
            for (int c = 0; c < 4; c++) acc[i][j][c] = 0.f;

    mainloop_nt(P + (size_t)i0 * SEQ, SEQ,
                vt + (size_t)e0 * SEQ, SEQ,
                (it + 1) * 2, smb, acc);

    float* C = Out + (size_t)b * SEQ * DMODEL;
    const int t = threadIdx.x, warp = t >> 5, lane = t & 31;
    const int wm = warp >> 1, wn = warp & 1;
    const int g = lane >> 2, tq = lane & 3;

    #pragma unroll
    for (int mt = 0; mt < 4; mt++) {
        const int r0 = i0 + wm * 64 + mt * 16 + g;
        #pragma unroll
        for (int nt = 0; nt < 8; nt++) {
            const int c0 = e0 + wn * 64 + nt * 8 + tq * 2;
            float* p0 = &C[(size_t)r0 * DMODEL + c0];
            float* p1 = &C[(size_t)(r0 + 8) * DMODEL + c0];
            p0[0] = acc[mt][nt][0];  p0[1] = acc[mt][nt][1];
            p1[0] = acc[mt][nt][2];  p1[1] = acc[mt][nt][3];
        }
    }
}

// ---------------------------------------------------------------------------
// Launch. Inputs: Q, K, V, Wq, Wk, Wv, bq, bk, bv, mask (mask == tril ones).
// ---------------------------------------------------------------------------
extern "C" void kernel_launch(void* const* d_in, const int* in_sizes, int n_in,
                              void* d_out, int out_size)
{
    const float* Q  = (const float*)d_in[0];
    const float* K  = (const float*)d_in[1];
    const float* V  = (const float*)d_in[2];
    const float* Wq = (const float*)d_in[3];
    const float* Wk = (const float*)d_in[4];
    const float* Wv = (const float*)d_in[5];
    const float* bq = (const float*)d_in[6];
    const float* bk = (const float*)d_in[7];
    const float* bv = (const float*)d_in[8];
    float* Out = (float*)d_out;

    cudaFuncSetAttribute(proj_kernel,   cudaFuncAttributeMaxDynamicSharedMemorySize, SMEM_BYTES);
    cudaFuncSetAttribute(scores_kernel, cudaFuncAttributeMaxDynamicSharedMemorySize, SMEM_BYTES);
    cudaFuncSetAttribute(out_kernel,    cudaFuncAttributeMaxDynamicSharedMemorySize, SMEM_BYTES);

    round_qkv<<<2048, 256>>>(Q, K, V);
    wtrans_kernel<<<dim3(32, 32, 3), dim3(32, 8)>>>(Wq, Wk, Wv);
    proj_kernel<<<dim3(DMODEL / 128, NROWS / 128, 3), NTHR, SMEM_BYTES>>>(bq, bk, bv);
    scores_kernel<<<dim3(SEQ / 128, SEQ / 128, BATCH), NTHR, SMEM_BYTES>>>();
    softmax_kernel<<<NROWS, 256>>>();
    out_kernel<<<dim3(DMODEL / 128, SEQ / 128, BATCH), NTHR, SMEM_BYTES>>>(Out);
}